// round 1
// baseline (speedup 1.0000x reference)
#include <cuda_runtime.h>
#include <math.h>

#define D_ 31
#define H_ 96
#define W_ 96
#define HW (H_*W_)        // 9216
#define VOX (D_*HW)       // 285696

// ---- scratch (device globals; no allocation allowed) ----
__device__ float g_conv[256 * VOX];   // conv output (max 256 ch)
__device__ float g_h  [16 * VOX];
__device__ float g_e0 [32 * VOX];
__device__ float g_e1 [64 * VOX];
__device__ float g_d0 [32 * VOX];
__device__ float g_d1 [16 * VOX];

__device__ __forceinline__ float sigm(float a) { return 1.0f / (1.0f + expf(-a)); }

// ---------------------------------------------------------------------------
// Direct 3x3x3 conv, SAME padding. Block: 256 threads -> tile 32(x) x 8(y) x 1(z),
// 8 output channels. Each thread: 2 co x 4 x-pixels.
// deconv=1: W_eff[co][ci][t] = w[ci][co][26-t]  (w shape (Cin, Cout, 3,3,3))
// ---------------------------------------------------------------------------
__global__ __launch_bounds__(256)
void conv3d_k(const float* __restrict__ in, const float* __restrict__ w,
              float* __restrict__ out, int Cin, int Cout, int deconv)
{
    __shared__ __align__(16) float in_s[3 * 10 * 36];   // z-halo x y-halo x x-halo(padded)
    __shared__ float w_s[8 * 27];

    const int tid = threadIdx.x;
    const int tx4 = tid & 7;          // x quad index (4 px each)
    const int ty  = (tid >> 3) & 7;   // y within tile
    const int cg  = tid >> 6;         // 0..3 -> 2 co each

    const int x0 = blockIdx.x * 32;
    const int y0 = (blockIdx.y % 12) * 8;
    const int zb = blockIdx.y / 12;
    const int coBase = blockIdx.z * 8;

    float acc[2][4] = {{0.f,0.f,0.f,0.f},{0.f,0.f,0.f,0.f}};

    for (int ci = 0; ci < Cin; ci++) {
        // cooperative halo-tile load for this ci
        for (int i = tid; i < 1080; i += 256) {
            int dz  = i / 360;
            int rem = i - dz * 360;
            int yy  = rem / 36;
            int xx  = rem - yy * 36;
            int z = zb + dz - 1, y = y0 + yy - 1, x = x0 + xx - 1;
            float v = 0.f;
            if ((unsigned)z < D_ && (unsigned)y < H_ && (unsigned)x < W_ && xx < 34)
                v = in[(size_t)ci * VOX + z * HW + y * W_ + x];
            in_s[i] = v;
        }
        // weights for 8 output channels of this ci
        if (tid < 216) {
            int co = tid / 27, t = tid - co * 27;
            int coG = coBase + co;
            float wv = 0.f;
            if (coG < Cout)
                wv = deconv ? w[((size_t)ci * Cout + coG) * 27 + (26 - t)]
                            : w[((size_t)coG * Cin + ci) * 27 + t];
            w_s[tid] = wv;
        }
        __syncthreads();

        const float* wp = &w_s[cg * 2 * 27];
        #pragma unroll
        for (int dz = 0; dz < 3; dz++) {
            #pragma unroll
            for (int dy = 0; dy < 3; dy++) {
                const float* row = &in_s[(dz * 10 + ty + dy) * 36 + tx4 * 4];
                float4 a4 = *(const float4*)row;
                float2 a2 = *(const float2*)(row + 4);
                float v[6] = {a4.x, a4.y, a4.z, a4.w, a2.x, a2.y};
                int tb = dz * 9 + dy * 3;
                #pragma unroll
                for (int dx = 0; dx < 3; dx++) {
                    float w0 = wp[tb + dx];
                    float w1 = wp[27 + tb + dx];
                    #pragma unroll
                    for (int p = 0; p < 4; p++) {
                        acc[0][p] += v[dx + p] * w0;
                        acc[1][p] += v[dx + p] * w1;
                    }
                }
            }
        }
        __syncthreads();
    }

    const int xo = x0 + tx4 * 4;
    const size_t base = (size_t)zb * HW + (y0 + ty) * W_ + xo;
    #pragma unroll
    for (int q = 0; q < 2; q++) {
        int coG = coBase + cg * 2 + q;
        if (coG < Cout) {
            float4 o = make_float4(acc[q][0], acc[q][1], acc[q][2], acc[q][3]);
            *(float4*)(out + (size_t)coG * VOX + base) = o;
        }
    }
}

// ---------------------------------------------------------------------------
// si_sru: g has 4C channels [Wx | ft | rt | X]; activations fused.
// One thread per (c, y, x); sequential scan over z. Optional skip-add.
// ---------------------------------------------------------------------------
__global__ void si_sru_k(const float* __restrict__ g, float* __restrict__ out,
                         const float* __restrict__ add, int C, int rev)
{
    int tid = blockIdx.x * blockDim.x + threadIdx.x;
    int total = C * HW;
    if (tid >= total) return;
    int c  = tid / HW;
    int yx = tid - c * HW;

    const float* Wp = g + (size_t)(0 * C + c) * VOX + yx;
    const float* Fp = g + (size_t)(1 * C + c) * VOX + yx;
    const float* Rp = g + (size_t)(2 * C + c) * VOX + yx;
    const float* Xp = g + (size_t)(3 * C + c) * VOX + yx;
    float*       op = out + (size_t)c * VOX + yx;
    const float* ap = add ? add + (size_t)c * VOX + yx : nullptr;

    int off = rev ? (D_ - 1) * HW : 0;
    int zs  = rev ? -HW : HW;

    float f = sigm(Fp[off]);
    float Cc = 1.f - f;
    float r = sigm(Rp[off]);
    float h = r * Cc + (1.f - r) * tanhf(Xp[off]);
    op[off] = h + (ap ? ap[off] : 0.f);

    for (int t = 1; t < D_; t++) {
        off += zs;
        f  = sigm(Fp[off]);
        Cc = f * Cc + (1.f - f) * tanhf(Wp[off]);
        r  = sigm(Rp[off]);
        h  = r * Cc + (1.f - r) * tanhf(Xp[off]);
        op[off] = h + (ap ? ap[off] : 0.f);
    }
}

// ---------------------------------------------------------------------------
// do_sru: g has 6C channels [Wx | ft | ft2 | rt | rt2 | X];
// out = fwd(ft,rt) + rev(ft2,rt2) (+ add). Two sequential passes per thread.
// ---------------------------------------------------------------------------
__global__ void do_sru_k(const float* __restrict__ g, float* __restrict__ out,
                         const float* __restrict__ add, int C)
{
    int tid = blockIdx.x * blockDim.x + threadIdx.x;
    int total = C * HW;
    if (tid >= total) return;
    int c  = tid / HW;
    int yx = tid - c * HW;

    const float* Wp = g + (size_t)(0 * C + c) * VOX + yx;
    const float* F1 = g + (size_t)(1 * C + c) * VOX + yx;
    const float* F2 = g + (size_t)(2 * C + c) * VOX + yx;
    const float* R1 = g + (size_t)(3 * C + c) * VOX + yx;
    const float* R2 = g + (size_t)(4 * C + c) * VOX + yx;
    const float* Xp = g + (size_t)(5 * C + c) * VOX + yx;
    float*       op = out + (size_t)c * VOX + yx;
    const float* ap = add ? add + (size_t)c * VOX + yx : nullptr;

    // forward pass (ft, rt) -> write
    {
        float f = sigm(F1[0]);
        float Cc = 1.f - f;
        float r = sigm(R1[0]);
        op[0] = r * Cc + (1.f - r) * tanhf(Xp[0]);
        int off = 0;
        for (int t = 1; t < D_; t++) {
            off += HW;
            f  = sigm(F1[off]);
            Cc = f * Cc + (1.f - f) * tanhf(Wp[off]);
            r  = sigm(R1[off]);
            op[off] = r * Cc + (1.f - r) * tanhf(Xp[off]);
        }
    }
    // reverse pass (ft2, rt2) -> accumulate (+ skip)
    {
        int off = (D_ - 1) * HW;
        float f = sigm(F2[off]);
        float Cc = 1.f - f;
        float r = sigm(R2[off]);
        float h = r * Cc + (1.f - r) * tanhf(Xp[off]);
        op[off] = op[off] + h + (ap ? ap[off] : 0.f);
        for (int t = 1; t < D_; t++) {
            off -= HW;
            f  = sigm(F2[off]);
            Cc = f * Cc + (1.f - f) * tanhf(Wp[off]);
            r  = sigm(R2[off]);
            h  = r * Cc + (1.f - r) * tanhf(Xp[off]);
            op[off] = op[off] + h + (ap ? ap[off] : 0.f);
        }
    }
}

// ---------------------------------------------------------------------------
static inline void conv_launch(const float* in, const float* w, float* out,
                               int Cin, int Cout, int deconv)
{
    dim3 grid(W_ / 32, (H_ / 8) * D_, (Cout + 7) / 8);
    conv3d_k<<<grid, 256>>>(in, w, out, Cin, Cout, deconv);
}

static inline void si_launch(const float* gbuf, float* out, const float* add,
                             int C, int rev)
{
    int n = C * HW;
    si_sru_k<<<(n + 255) / 256, 256>>>(gbuf, out, add, C, rev);
}

static inline void do_launch(const float* gbuf, float* out, const float* add, int C)
{
    int n = C * HW;
    do_sru_k<<<(n + 255) / 256, 256>>>(gbuf, out, add, C);
}

extern "C" void kernel_launch(void* const* d_in, const int* in_sizes, int n_in,
                              void* d_out, int out_size)
{
    (void)in_sizes; (void)n_in; (void)out_size;
    const float* x      = (const float*)d_in[0];
    const float* w_head = (const float*)d_in[1];
    const float* w_e0   = (const float*)d_in[2];
    const float* w_e1   = (const float*)d_in[3];
    const float* w_d0   = (const float*)d_in[4];
    const float* w_d1   = (const float*)d_in[5];
    const float* w_tail = (const float*)d_in[6];
    float* out = (float*)d_out;

    float *gc, *gh, *ge0, *ge1, *gd0, *gd1;
    cudaGetSymbolAddress((void**)&gc,  g_conv);
    cudaGetSymbolAddress((void**)&gh,  g_h);
    cudaGetSymbolAddress((void**)&ge0, g_e0);
    cudaGetSymbolAddress((void**)&ge1, g_e1);
    cudaGetSymbolAddress((void**)&gd0, g_d0);
    cudaGetSymbolAddress((void**)&gd1, g_d1);

    // h = do_sru(x, w_head)
    conv_launch(x, w_head, gc, 1, 96, 0);
    do_launch(gc, gh, nullptr, 16);
    // e0 = si_sru(h, w_e0, fwd)
    conv_launch(gh, w_e0, gc, 16, 128, 0);
    si_launch(gc, ge0, nullptr, 32, 0);
    // e1 = si_sru(e0, w_e1, rev)
    conv_launch(ge0, w_e1, gc, 32, 256, 0);
    si_launch(gc, ge1, nullptr, 64, 1);
    // d0 = si_sru(e1, w_d0, fwd, deconv) + e0
    conv_launch(ge1, w_d0, gc, 64, 128, 1);
    si_launch(gc, gd0, ge0, 32, 0);
    // d1 = si_sru(d0, w_d1, rev, deconv) + h
    conv_launch(gd0, w_d1, gc, 32, 64, 1);
    si_launch(gc, gd1, gh, 16, 1);
    // out = do_sru(d1, w_tail, deconv) + x
    conv_launch(gd1, w_tail, gc, 16, 6, 1);
    do_launch(gc, out, x, 1);
}

// round 2
// speedup vs baseline: 1.4941x; 1.4941x over previous
#include <cuda_runtime.h>
#include <math.h>

#define D_ 31
#define H_ 96
#define W_ 96
#define HW (H_*W_)        // 9216
#define VOX (D_*HW)       // 285696

// ---- scratch (device globals; no allocation allowed) ----
__device__ float g_conv[256 * VOX];   // conv output (max 256 ch)
__device__ float g_h  [16 * VOX];
__device__ float g_e0 [32 * VOX];
__device__ float g_e1 [64 * VOX];
__device__ float g_d0 [32 * VOX];
__device__ float g_d1 [16 * VOX];

__device__ __forceinline__ float sigm(float a) { return 1.0f / (1.0f + expf(-a)); }

typedef unsigned long long u64;

__device__ __forceinline__ void fma2(u64& d, u64 a, u64 b) {
    asm("fma.rn.f32x2 %0, %1, %2, %0;" : "+l"(d) : "l"(a), "l"(b));
}
__device__ __forceinline__ u64 pk2(float x, float y) {
    u64 r; asm("mov.b64 %0, {%1, %2};" : "=l"(r) : "f"(x), "f"(y)); return r;
}
__device__ __forceinline__ float2 unpk2(u64 a) {
    float x, y; asm("mov.b64 {%0, %1}, %2;" : "=f"(x), "=f"(y) : "l"(a));
    return make_float2(x, y);
}

// ---------------------------------------------------------------------------
// Direct 3x3x3 conv, SAME padding, f32x2 packed math.
// Block: 256 threads -> spatial tile 32(x) x 8(y) x 1(z), 16 output channels.
// Each thread: 4 co x 4 x-pixels (as 8 f32x2 accumulators).
// deconv=1: W_eff[co][ci][t] = w[ci][co][26-t]  (w shape (Cin, Cout, 3,3,3))
// Register-prefetch of next ci's halo + weights overlaps gmem latency.
// ---------------------------------------------------------------------------
#define HALO 1080           // 3 * 10 * 36
#define WTOT 432            // 16 co * 27 taps

__global__ __launch_bounds__(256)
void conv3d_k(const float* __restrict__ in, const float* __restrict__ w,
              float* __restrict__ out, int Cin, int Cout, int deconv)
{
    __shared__ __align__(16) float  in_s[HALO];
    __shared__ __align__(8)  float2 w_s2[WTOT];   // weights duplicated (w,w)

    const int tid = threadIdx.x;
    const int tx4 = tid & 7;          // x quad index (4 px each)
    const int ty  = (tid >> 3) & 7;   // y within tile
    const int cg  = tid >> 6;         // 0..3 -> 4 co each

    const int x0 = blockIdx.x * 32;
    const int y0 = (blockIdx.y % 12) * 8;
    const int zb = blockIdx.y / 12;
    const int coBase = blockIdx.z * 16;

    // ---- per-thread halo load descriptors (loop-invariant) ----
    int  hoff[5]; bool hval[5];
    #pragma unroll
    for (int k = 0; k < 5; k++) {
        int i = tid + k * 256;
        if (i < HALO) {
            int dz  = i / 360;
            int rem = i - dz * 360;
            int yy  = rem / 36;
            int xx  = rem - yy * 36;
            int z = zb + dz - 1, y = y0 + yy - 1, x = x0 + xx - 1;
            hval[k] = ((unsigned)z < D_) && ((unsigned)y < H_) && ((unsigned)x < W_) && (xx < 34);
            hoff[k] = z * HW + y * W_ + x;
        } else { hval[k] = false; hoff[k] = 0; }
    }
    // ---- per-thread weight load descriptors ----
    int wbase[2]; bool wvalid[2];
    const int wstride = deconv ? Cout * 27 : 27;
    #pragma unroll
    for (int k = 0; k < 2; k++) {
        int idx = tid + k * 256;
        if (idx < WTOT) {
            int co = idx / 27, t = idx - co * 27;
            int coG = coBase + co;
            wvalid[k] = (coG < Cout);
            wbase[k]  = deconv ? (coG * 27 + (26 - t)) : (coG * Cin * 27 + t);
        } else { wvalid[k] = false; wbase[k] = 0; }
    }

    u64 acc[4][2];
    #pragma unroll
    for (int c = 0; c < 4; c++) { acc[c][0] = 0ull; acc[c][1] = 0ull; }

    // ---- prefetch ci = 0 ----
    float hreg[5], wreg[2];
    #pragma unroll
    for (int k = 0; k < 5; k++) hreg[k] = hval[k] ? __ldg(in + hoff[k]) : 0.f;
    #pragma unroll
    for (int k = 0; k < 2; k++) wreg[k] = wvalid[k] ? __ldg(w + wbase[k]) : 0.f;

    for (int ci = 0; ci < Cin; ci++) {
        // stage current ci into smem
        #pragma unroll
        for (int k = 0; k < 5; k++) {
            int i = tid + k * 256;
            if (i < HALO) in_s[i] = hreg[k];
        }
        #pragma unroll
        for (int k = 0; k < 2; k++) {
            int idx = tid + k * 256;
            if (idx < WTOT) w_s2[idx] = make_float2(wreg[k], wreg[k]);
        }
        __syncthreads();

        // prefetch next ci while computing
        if (ci + 1 < Cin) {
            const float* inp = in + (size_t)(ci + 1) * VOX;
            #pragma unroll
            for (int k = 0; k < 5; k++) hreg[k] = hval[k] ? __ldg(inp + hoff[k]) : 0.f;
            const float* wp_ = w + (size_t)(ci + 1) * wstride;
            #pragma unroll
            for (int k = 0; k < 2; k++) wreg[k] = wvalid[k] ? __ldg(wp_ + wbase[k]) : 0.f;
        }

        const float2* wp = &w_s2[cg * 4 * 27];
        #pragma unroll
        for (int dz = 0; dz < 3; dz++) {
            #pragma unroll
            for (int dy = 0; dy < 3; dy++) {
                const float* row = &in_s[(dz * 10 + ty + dy) * 36 + tx4 * 4];
                float4 a4 = *(const float4*)row;
                float2 a2 = *(const float2*)(row + 4);
                u64 p01 = pk2(a4.x, a4.y);
                u64 p12 = pk2(a4.y, a4.z);
                u64 p23 = pk2(a4.z, a4.w);
                u64 p34 = pk2(a4.w, a2.x);
                u64 p45 = pk2(a2.x, a2.y);
                const int tb = dz * 9 + dy * 3;
                #pragma unroll
                for (int co = 0; co < 4; co++) {
                    const float2* wc = wp + co * 27 + tb;
                    u64 w0 = *(const u64*)(wc + 0);
                    fma2(acc[co][0], p01, w0); fma2(acc[co][1], p23, w0);
                    u64 w1 = *(const u64*)(wc + 1);
                    fma2(acc[co][0], p12, w1); fma2(acc[co][1], p34, w1);
                    u64 w2 = *(const u64*)(wc + 2);
                    fma2(acc[co][0], p23, w2); fma2(acc[co][1], p45, w2);
                }
            }
        }
        __syncthreads();
    }

    const int xo = x0 + tx4 * 4;
    const size_t base = (size_t)zb * HW + (y0 + ty) * W_ + xo;
    #pragma unroll
    for (int co = 0; co < 4; co++) {
        int coG = coBase + cg * 4 + co;
        if (coG < Cout) {
            float2 lo = unpk2(acc[co][0]);
            float2 hi = unpk2(acc[co][1]);
            float4 o = make_float4(lo.x, lo.y, hi.x, hi.y);
            *(float4*)(out + (size_t)coG * VOX + base) = o;
        }
    }
}

// ---------------------------------------------------------------------------
// si_sru: g has 4C channels [Wx | ft | rt | X]; activations fused.
// One thread per (c, y, x); sequential scan over z. Optional skip-add.
// ---------------------------------------------------------------------------
__global__ void si_sru_k(const float* __restrict__ g, float* __restrict__ out,
                         const float* __restrict__ add, int C, int rev)
{
    int tid = blockIdx.x * blockDim.x + threadIdx.x;
    int total = C * HW;
    if (tid >= total) return;
    int c  = tid / HW;
    int yx = tid - c * HW;

    const float* Wp = g + (size_t)(0 * C + c) * VOX + yx;
    const float* Fp = g + (size_t)(1 * C + c) * VOX + yx;
    const float* Rp = g + (size_t)(2 * C + c) * VOX + yx;
    const float* Xp = g + (size_t)(3 * C + c) * VOX + yx;
    float*       op = out + (size_t)c * VOX + yx;
    const float* ap = add ? add + (size_t)c * VOX + yx : nullptr;

    int off = rev ? (D_ - 1) * HW : 0;
    int zs  = rev ? -HW : HW;

    float f = sigm(Fp[off]);
    float Cc = 1.f - f;
    float r = sigm(Rp[off]);
    float h = r * Cc + (1.f - r) * tanhf(Xp[off]);
    op[off] = h + (ap ? ap[off] : 0.f);

    for (int t = 1; t < D_; t++) {
        off += zs;
        f  = sigm(Fp[off]);
        Cc = f * Cc + (1.f - f) * tanhf(Wp[off]);
        r  = sigm(Rp[off]);
        h  = r * Cc + (1.f - r) * tanhf(Xp[off]);
        op[off] = h + (ap ? ap[off] : 0.f);
    }
}

// ---------------------------------------------------------------------------
// do_sru: g has 6C channels [Wx | ft | ft2 | rt | rt2 | X];
// out = fwd(ft,rt) + rev(ft2,rt2) (+ add). Two sequential passes per thread.
// ---------------------------------------------------------------------------
__global__ void do_sru_k(const float* __restrict__ g, float* __restrict__ out,
                         const float* __restrict__ add, int C)
{
    int tid = blockIdx.x * blockDim.x + threadIdx.x;
    int total = C * HW;
    if (tid >= total) return;
    int c  = tid / HW;
    int yx = tid - c * HW;

    const float* Wp = g + (size_t)(0 * C + c) * VOX + yx;
    const float* F1 = g + (size_t)(1 * C + c) * VOX + yx;
    const float* F2 = g + (size_t)(2 * C + c) * VOX + yx;
    const float* R1 = g + (size_t)(3 * C + c) * VOX + yx;
    const float* R2 = g + (size_t)(4 * C + c) * VOX + yx;
    const float* Xp = g + (size_t)(5 * C + c) * VOX + yx;
    float*       op = out + (size_t)c * VOX + yx;
    const float* ap = add ? add + (size_t)c * VOX + yx : nullptr;

    // forward pass (ft, rt) -> write
    {
        float f = sigm(F1[0]);
        float Cc = 1.f - f;
        float r = sigm(R1[0]);
        op[0] = r * Cc + (1.f - r) * tanhf(Xp[0]);
        int off = 0;
        for (int t = 1; t < D_; t++) {
            off += HW;
            f  = sigm(F1[off]);
            Cc = f * Cc + (1.f - f) * tanhf(Wp[off]);
            r  = sigm(R1[off]);
            op[off] = r * Cc + (1.f - r) * tanhf(Xp[off]);
        }
    }
    // reverse pass (ft2, rt2) -> accumulate (+ skip)
    {
        int off = (D_ - 1) * HW;
        float f = sigm(F2[off]);
        float Cc = 1.f - f;
        float r = sigm(R2[off]);
        float h = r * Cc + (1.f - r) * tanhf(Xp[off]);
        op[off] = op[off] + h + (ap ? ap[off] : 0.f);
        for (int t = 1; t < D_; t++) {
            off -= HW;
            f  = sigm(F2[off]);
            Cc = f * Cc + (1.f - f) * tanhf(Wp[off]);
            r  = sigm(R2[off]);
            h  = r * Cc + (1.f - r) * tanhf(Xp[off]);
            op[off] = op[off] + h + (ap ? ap[off] : 0.f);
        }
    }
}

// ---------------------------------------------------------------------------
static inline void conv_launch(const float* in, const float* w, float* out,
                               int Cin, int Cout, int deconv)
{
    dim3 grid(W_ / 32, (H_ / 8) * D_, (Cout + 15) / 16);
    conv3d_k<<<grid, 256>>>(in, w, out, Cin, Cout, deconv);
}

static inline void si_launch(const float* gbuf, float* out, const float* add,
                             int C, int rev)
{
    int n = C * HW;
    si_sru_k<<<(n + 255) / 256, 256>>>(gbuf, out, add, C, rev);
}

static inline void do_launch(const float* gbuf, float* out, const float* add, int C)
{
    int n = C * HW;
    do_sru_k<<<(n + 255) / 256, 256>>>(gbuf, out, add, C);
}

extern "C" void kernel_launch(void* const* d_in, const int* in_sizes, int n_in,
                              void* d_out, int out_size)
{
    (void)in_sizes; (void)n_in; (void)out_size;
    const float* x      = (const float*)d_in[0];
    const float* w_head = (const float*)d_in[1];
    const float* w_e0   = (const float*)d_in[2];
    const float* w_e1   = (const float*)d_in[3];
    const float* w_d0   = (const float*)d_in[4];
    const float* w_d1   = (const float*)d_in[5];
    const float* w_tail = (const float*)d_in[6];
    float* out = (float*)d_out;

    float *gc, *gh, *ge0, *ge1, *gd0, *gd1;
    cudaGetSymbolAddress((void**)&gc,  g_conv);
    cudaGetSymbolAddress((void**)&gh,  g_h);
    cudaGetSymbolAddress((void**)&ge0, g_e0);
    cudaGetSymbolAddress((void**)&ge1, g_e1);
    cudaGetSymbolAddress((void**)&gd0, g_d0);
    cudaGetSymbolAddress((void**)&gd1, g_d1);

    // h = do_sru(x, w_head)
    conv_launch(x, w_head, gc, 1, 96, 0);
    do_launch(gc, gh, nullptr, 16);
    // e0 = si_sru(h, w_e0, fwd)
    conv_launch(gh, w_e0, gc, 16, 128, 0);
    si_launch(gc, ge0, nullptr, 32, 0);
    // e1 = si_sru(e0, w_e1, rev)
    conv_launch(ge0, w_e1, gc, 32, 256, 0);
    si_launch(gc, ge1, nullptr, 64, 1);
    // d0 = si_sru(e1, w_d0, fwd, deconv) + e0
    conv_launch(ge1, w_d0, gc, 64, 128, 1);
    si_launch(gc, gd0, ge0, 32, 0);
    // d1 = si_sru(d0, w_d1, rev, deconv) + h
    conv_launch(gd0, w_d1, gc, 32, 64, 1);
    si_launch(gc, gd1, gh, 16, 1);
    // out = do_sru(d1, w_tail, deconv) + x
    conv_launch(gd1, w_tail, gc, 16, 6, 1);
    do_launch(gc, out, x, 1);
}

// round 4
// speedup vs baseline: 1.5454x; 1.0344x over previous
#include <cuda_runtime.h>
#include <math.h>

#define D_ 31
#define H_ 96
#define W_ 96
#define HW (H_*W_)        // 9216
#define VOX (D_*HW)       // 285696

// ---- scratch (device globals; no allocation allowed) ----
__device__ float g_conv[256 * VOX];   // conv output (max 256 ch)
__device__ float g_h  [16 * VOX];
__device__ float g_e0 [32 * VOX];
__device__ float g_e1 [64 * VOX];
__device__ float g_d0 [32 * VOX];
__device__ float g_d1 [16 * VOX];

__device__ __forceinline__ float sigm(float a) { return 1.0f / (1.0f + expf(-a)); }

typedef unsigned long long u64;

__device__ __forceinline__ void fma2(u64& d, u64 a, u64 b) {
    asm("fma.rn.f32x2 %0, %1, %2, %0;" : "+l"(d) : "l"(a), "l"(b));
}
__device__ __forceinline__ u64 pk2(float x, float y) {
    u64 r; asm("mov.b64 %0, {%1, %2};" : "=l"(r) : "f"(x), "f"(y)); return r;
}
__device__ __forceinline__ float2 unpk2(u64 a) {
    float x, y; asm("mov.b64 {%0, %1}, %2;" : "=f"(x), "=f"(y) : "l"(a));
    return make_float2(x, y);
}

// ---------------------------------------------------------------------------
// Direct 3x3x3 conv, SAME padding, f32x2 packed math.
// Block: 256 threads -> spatial tile 32(x) x 8(y) x 1(z), 32 output channels.
// Each thread: 4 co x 8 x-pixels (16 f32x2 accumulators).
// deconv=1: W_eff[co][ci][t] = w[ci][co][26-t]  (w shape (Cin, Cout, 3,3,3))
// Register-prefetch of next ci's halo + weights overlaps gmem latency.
// ---------------------------------------------------------------------------
#define HALO 1080           // 3 * 10 * 36
#define WTOT 864            // 32 co * 27 taps

__global__ __launch_bounds__(256, 2)
void conv3d_k(const float* __restrict__ in, const float* __restrict__ w,
              float* __restrict__ out, int Cin, int Cout, int deconv)
{
    __shared__ __align__(16) float  in_s[HALO];
    __shared__ __align__(8)  float2 w_s2[WTOT];   // weights duplicated (w,w)

    const int tid = threadIdx.x;
    const int tx  = tid & 3;          // x group (8 px each)
    const int ty  = (tid >> 2) & 7;   // y within tile
    const int cg  = tid >> 5;         // 0..7 -> 4 co each (warp-uniform)

    const int x0 = blockIdx.x * 32;
    const int y0 = (blockIdx.y % 12) * 8;
    const int zb = blockIdx.y / 12;
    const int coBase = blockIdx.z * 32;

    // ---- per-thread halo load descriptors (loop-invariant) ----
    int  hoff[5]; bool hval[5];
    #pragma unroll
    for (int k = 0; k < 5; k++) {
        int i = tid + k * 256;
        if (i < HALO) {
            int dz  = i / 360;
            int rem = i - dz * 360;
            int yy  = rem / 36;
            int xx  = rem - yy * 36;
            int z = zb + dz - 1, y = y0 + yy - 1, x = x0 + xx - 1;
            hval[k] = ((unsigned)z < D_) && ((unsigned)y < H_) && ((unsigned)x < W_) && (xx < 34);
            hoff[k] = z * HW + y * W_ + x;
        } else { hval[k] = false; hoff[k] = 0; }
    }
    // ---- per-thread weight load descriptors ----
    int wbase[4]; bool wvalid[4];
    const int wstride = deconv ? Cout * 27 : 27;
    #pragma unroll
    for (int k = 0; k < 4; k++) {
        int idx = tid + k * 256;
        if (idx < WTOT) {
            int co = idx / 27, t = idx - co * 27;
            int coG = coBase + co;
            wvalid[k] = (coG < Cout);
            wbase[k]  = deconv ? (coG * 27 + (26 - t)) : (coG * Cin * 27 + t);
        } else { wvalid[k] = false; wbase[k] = 0; }
    }

    u64 acc[4][4];
    #pragma unroll
    for (int c = 0; c < 4; c++)
        #pragma unroll
        for (int j = 0; j < 4; j++) acc[c][j] = 0ull;

    // ---- prefetch ci = 0 ----
    float hreg[5], wreg[4];
    #pragma unroll
    for (int k = 0; k < 5; k++) hreg[k] = hval[k] ? __ldg(in + hoff[k]) : 0.f;
    #pragma unroll
    for (int k = 0; k < 4; k++) wreg[k] = wvalid[k] ? __ldg(w + wbase[k]) : 0.f;

    for (int ci = 0; ci < Cin; ci++) {
        // stage current ci into smem
        #pragma unroll
        for (int k = 0; k < 5; k++) {
            int i = tid + k * 256;
            if (i < HALO) in_s[i] = hreg[k];
        }
        #pragma unroll
        for (int k = 0; k < 4; k++) {
            int idx = tid + k * 256;
            if (idx < WTOT) w_s2[idx] = make_float2(wreg[k], wreg[k]);
        }
        __syncthreads();

        // prefetch next ci while computing
        if (ci + 1 < Cin) {
            const float* inp = in + (size_t)(ci + 1) * VOX;
            #pragma unroll
            for (int k = 0; k < 5; k++) hreg[k] = hval[k] ? __ldg(inp + hoff[k]) : 0.f;
            const float* wp_ = w + (size_t)(ci + 1) * wstride;
            #pragma unroll
            for (int k = 0; k < 4; k++) wreg[k] = wvalid[k] ? __ldg(wp_ + wbase[k]) : 0.f;
        }

        const float2* wp = &w_s2[cg * 4 * 27];
        #pragma unroll
        for (int dz = 0; dz < 3; dz++) {
            #pragma unroll
            for (int dy = 0; dy < 3; dy++) {
                const float* row = &in_s[(dz * 10 + ty + dy) * 36 + tx * 8];
                float4 a4 = *(const float4*)row;
                float4 b4 = *(const float4*)(row + 4);
                float2 c2 = *(const float2*)(row + 8);
                float v[10] = {a4.x, a4.y, a4.z, a4.w, b4.x, b4.y, b4.z, b4.w, c2.x, c2.y};
                u64 p[9];
                #pragma unroll
                for (int i = 0; i < 9; i++) p[i] = pk2(v[i], v[i + 1]);
                const int tb = dz * 9 + dy * 3;
                #pragma unroll
                for (int co = 0; co < 4; co++) {
                    const float2* wc = wp + co * 27 + tb;
                    u64 w0 = *(const u64*)(wc + 0);
                    fma2(acc[co][0], p[0], w0); fma2(acc[co][1], p[2], w0);
                    fma2(acc[co][2], p[4], w0); fma2(acc[co][3], p[6], w0);
                    u64 w1 = *(const u64*)(wc + 1);
                    fma2(acc[co][0], p[1], w1); fma2(acc[co][1], p[3], w1);
                    fma2(acc[co][2], p[5], w1); fma2(acc[co][3], p[7], w1);
                    u64 w2 = *(const u64*)(wc + 2);
                    fma2(acc[co][0], p[2], w2); fma2(acc[co][1], p[4], w2);
                    fma2(acc[co][2], p[6], w2); fma2(acc[co][3], p[8], w2);
                }
            }
        }
        __syncthreads();
    }

    const int xo = x0 + tx * 8;
    const size_t base = (size_t)zb * HW + (y0 + ty) * W_ + xo;
    #pragma unroll
    for (int co = 0; co < 4; co++) {
        int coG = coBase + cg * 4 + co;
        if (coG < Cout) {
            float2 q0 = unpk2(acc[co][0]);
            float2 q1 = unpk2(acc[co][1]);
            float2 q2 = unpk2(acc[co][2]);
            float2 q3 = unpk2(acc[co][3]);
            float* op = out + (size_t)coG * VOX + base;
            *(float4*)(op + 0) = make_float4(q0.x, q0.y, q1.x, q1.y);
            *(float4*)(op + 4) = make_float4(q2.x, q2.y, q3.x, q3.y);
        }
    }
}

// ---------------------------------------------------------------------------
// si_sru: g has 4C channels [Wx | ft | rt | X]; activations fused.
// ---------------------------------------------------------------------------
__global__ void si_sru_k(const float* __restrict__ g, float* __restrict__ out,
                         const float* __restrict__ add, int C, int rev)
{
    int tid = blockIdx.x * blockDim.x + threadIdx.x;
    int total = C * HW;
    if (tid >= total) return;
    int c  = tid / HW;
    int yx = tid - c * HW;

    const float* Wp = g + (size_t)(0 * C + c) * VOX + yx;
    const float* Fp = g + (size_t)(1 * C + c) * VOX + yx;
    const float* Rp = g + (size_t)(2 * C + c) * VOX + yx;
    const float* Xp = g + (size_t)(3 * C + c) * VOX + yx;
    float*       op = out + (size_t)c * VOX + yx;
    const float* ap = add ? add + (size_t)c * VOX + yx : nullptr;

    int off = rev ? (D_ - 1) * HW : 0;
    int zs  = rev ? -HW : HW;

    float f = sigm(Fp[off]);
    float Cc = 1.f - f;
    float r = sigm(Rp[off]);
    float h = r * Cc + (1.f - r) * tanhf(Xp[off]);
    op[off] = h + (ap ? ap[off] : 0.f);

    for (int t = 1; t < D_; t++) {
        off += zs;
        f  = sigm(Fp[off]);
        Cc = f * Cc + (1.f - f) * tanhf(Wp[off]);
        r  = sigm(Rp[off]);
        h  = r * Cc + (1.f - r) * tanhf(Xp[off]);
        op[off] = h + (ap ? ap[off] : 0.f);
    }
}

// ---------------------------------------------------------------------------
// do_sru: g has 6C channels [Wx | ft | ft2 | rt | rt2 | X];
// ---------------------------------------------------------------------------
__global__ void do_sru_k(const float* __restrict__ g, float* __restrict__ out,
                         const float* __restrict__ add, int C)
{
    int tid = blockIdx.x * blockDim.x + threadIdx.x;
    int total = C * HW;
    if (tid >= total) return;
    int c  = tid / HW;
    int yx = tid - c * HW;

    const float* Wp = g + (size_t)(0 * C + c) * VOX + yx;
    const float* F1 = g + (size_t)(1 * C + c) * VOX + yx;
    const float* F2 = g + (size_t)(2 * C + c) * VOX + yx;
    const float* R1 = g + (size_t)(3 * C + c) * VOX + yx;
    const float* R2 = g + (size_t)(4 * C + c) * VOX + yx;
    const float* Xp = g + (size_t)(5 * C + c) * VOX + yx;
    float*       op = out + (size_t)c * VOX + yx;
    const float* ap = add ? add + (size_t)c * VOX + yx : nullptr;

    {
        float f = sigm(F1[0]);
        float Cc = 1.f - f;
        float r = sigm(R1[0]);
        op[0] = r * Cc + (1.f - r) * tanhf(Xp[0]);
        int off = 0;
        for (int t = 1; t < D_; t++) {
            off += HW;
            f  = sigm(F1[off]);
            Cc = f * Cc + (1.f - f) * tanhf(Wp[off]);
            r  = sigm(R1[off]);
            op[off] = r * Cc + (1.f - r) * tanhf(Xp[off]);
        }
    }
    {
        int off = (D_ - 1) * HW;
        float f = sigm(F2[off]);
        float Cc = 1.f - f;
        float r = sigm(R2[off]);
        float h = r * Cc + (1.f - r) * tanhf(Xp[off]);
        op[off] = op[off] + h + (ap ? ap[off] : 0.f);
        for (int t = 1; t < D_; t++) {
            off -= HW;
            f  = sigm(F2[off]);
            Cc = f * Cc + (1.f - f) * tanhf(Wp[off]);
            r  = sigm(R2[off]);
            h  = r * Cc + (1.f - r) * tanhf(Xp[off]);
            op[off] = op[off] + h + (ap ? ap[off] : 0.f);
        }
    }
}

// ---------------------------------------------------------------------------
static inline void conv_launch(const float* in, const float* w, float* out,
                               int Cin, int Cout, int deconv)
{
    dim3 grid(W_ / 32, (H_ / 8) * D_, (Cout + 31) / 32);
    conv3d_k<<<grid, 256>>>(in, w, out, Cin, Cout, deconv);
}

static inline void si_launch(const float* gbuf, float* out, const float* add,
                             int C, int rev)
{
    int n = C * HW;
    si_sru_k<<<(n + 255) / 256, 256>>>(gbuf, out, add, C, rev);
}

static inline void do_launch(const float* gbuf, float* out, const float* add, int C)
{
    int n = C * HW;
    do_sru_k<<<(n + 255) / 256, 256>>>(gbuf, out, add, C);
}

extern "C" void kernel_launch(void* const* d_in, const int* in_sizes, int n_in,
                              void* d_out, int out_size)
{
    (void)in_sizes; (void)n_in; (void)out_size;
    const float* x      = (const float*)d_in[0];
    const float* w_head = (const float*)d_in[1];
    const float* w_e0   = (const float*)d_in[2];
    const float* w_e1   = (const float*)d_in[3];
    const float* w_d0   = (const float*)d_in[4];
    const float* w_d1   = (const float*)d_in[5];
    const float* w_tail = (const float*)d_in[6];
    float* out = (float*)d_out;

    float *gc, *gh, *ge0, *ge1, *gd0, *gd1;
    cudaGetSymbolAddress((void**)&gc,  g_conv);
    cudaGetSymbolAddress((void**)&gh,  g_h);
    cudaGetSymbolAddress((void**)&ge0, g_e0);
    cudaGetSymbolAddress((void**)&ge1, g_e1);
    cudaGetSymbolAddress((void**)&gd0, g_d0);
    cudaGetSymbolAddress((void**)&gd1, g_d1);

    // h = do_sru(x, w_head)
    conv_launch(x, w_head, gc, 1, 96, 0);
    do_launch(gc, gh, nullptr, 16);
    // e0 = si_sru(h, w_e0, fwd)
    conv_launch(gh, w_e0, gc, 16, 128, 0);
    si_launch(gc, ge0, nullptr, 32, 0);
    // e1 = si_sru(e0, w_e1, rev)
    conv_launch(ge0, w_e1, gc, 32, 256, 0);
    si_launch(gc, ge1, nullptr, 64, 1);
    // d0 = si_sru(e1, w_d0, fwd, deconv) + e0
    conv_launch(ge1, w_d0, gc, 64, 128, 1);
    si_launch(gc, gd0, ge0, 32, 0);
    // d1 = si_sru(d0, w_d1, rev, deconv) + h
    conv_launch(gd0, w_d1, gc, 32, 64, 1);
    si_launch(gc, gd1, gh, 16, 1);
    // out = do_sru(d1, w_tail, deconv) + x
    conv_launch(gd1, w_tail, gc, 16, 6, 1);
    do_launch(gc, out, x, 1);
}

// round 5
// speedup vs baseline: 1.5521x; 1.0043x over previous
#include <cuda_runtime.h>
#include <math.h>

#define D_ 31
#define H_ 96
#define W_ 96
#define HW (H_*W_)        // 9216
#define VOX (D_*HW)       // 285696

// ---- scratch (device globals; no allocation allowed) ----
__device__ float g_conv[256 * VOX];   // conv output (max 256 ch)
__device__ float g_h  [16 * VOX];
__device__ float g_e0 [32 * VOX];
__device__ float g_e1 [64 * VOX];
__device__ float g_d0 [32 * VOX];
__device__ float g_d1 [16 * VOX];

__device__ __forceinline__ float sigm(float a) { return 1.0f / (1.0f + expf(-a)); }

typedef unsigned long long u64;

__device__ __forceinline__ void fma2(u64& d, u64 a, u64 b) {
    asm("fma.rn.f32x2 %0, %1, %2, %0;" : "+l"(d) : "l"(a), "l"(b));
}
__device__ __forceinline__ u64 pk2(float x, float y) {
    u64 r; asm("mov.b64 %0, {%1, %2};" : "=l"(r) : "f"(x), "f"(y)); return r;
}
__device__ __forceinline__ float2 unpk2(u64 a) {
    float x, y; asm("mov.b64 {%0, %1}, %2;" : "=f"(x), "=f"(y) : "l"(a));
    return make_float2(x, y);
}

// ---------------------------------------------------------------------------
// Direct 3x3x3 conv, SAME padding, f32x2 packed math.
// Block: 256 threads -> spatial tile 32(x) x 8(y) x 1(z), 32 output channels.
// Each thread: 4 co x 8 x-pixels (16 f32x2 accumulators).
// deconv=1: W_eff[co][ci][t] = w[ci][co][26-t]  (w shape (Cin, Cout, 3,3,3))
// Register-prefetch of next ci's halo + weights overlaps gmem latency.
// ---------------------------------------------------------------------------
#define HALO 1080           // 3 * 10 * 36
#define WTOT 864            // 32 co * 27 taps

__global__ __launch_bounds__(256, 2)
void conv3d_k(const float* __restrict__ in, const float* __restrict__ w,
              float* __restrict__ out, int Cin, int Cout, int deconv)
{
    __shared__ __align__(16) float  in_s[HALO];
    __shared__ __align__(8)  float2 w_s2[WTOT];   // weights duplicated (w,w)

    const int tid = threadIdx.x;
    const int tx  = tid & 3;          // x group (8 px each)
    const int ty  = (tid >> 2) & 7;   // y within tile
    const int cg  = tid >> 5;         // 0..7 -> 4 co each (warp-uniform)

    const int x0 = blockIdx.x * 32;
    const int y0 = (blockIdx.y % 12) * 8;
    const int zb = blockIdx.y / 12;
    const int coBase = blockIdx.z * 32;

    // ---- per-thread halo load descriptors (loop-invariant) ----
    int  hoff[5]; bool hval[5];
    #pragma unroll
    for (int k = 0; k < 5; k++) {
        int i = tid + k * 256;
        if (i < HALO) {
            int dz  = i / 360;
            int rem = i - dz * 360;
            int yy  = rem / 36;
            int xx  = rem - yy * 36;
            int z = zb + dz - 1, y = y0 + yy - 1, x = x0 + xx - 1;
            hval[k] = ((unsigned)z < D_) && ((unsigned)y < H_) && ((unsigned)x < W_) && (xx < 34);
            hoff[k] = z * HW + y * W_ + x;
        } else { hval[k] = false; hoff[k] = 0; }
    }
    // ---- per-thread weight load descriptors ----
    int wbase[4]; bool wvalid[4];
    const int wstride = deconv ? Cout * 27 : 27;
    #pragma unroll
    for (int k = 0; k < 4; k++) {
        int idx = tid + k * 256;
        if (idx < WTOT) {
            int co = idx / 27, t = idx - co * 27;
            int coG = coBase + co;
            wvalid[k] = (coG < Cout);
            wbase[k]  = deconv ? (coG * 27 + (26 - t)) : (coG * Cin * 27 + t);
        } else { wvalid[k] = false; wbase[k] = 0; }
    }

    u64 acc[4][4];
    #pragma unroll
    for (int c = 0; c < 4; c++)
        #pragma unroll
        for (int j = 0; j < 4; j++) acc[c][j] = 0ull;

    // ---- prefetch ci = 0 ----
    float hreg[5], wreg[4];
    #pragma unroll
    for (int k = 0; k < 5; k++) hreg[k] = hval[k] ? __ldg(in + hoff[k]) : 0.f;
    #pragma unroll
    for (int k = 0; k < 4; k++) wreg[k] = wvalid[k] ? __ldg(w + wbase[k]) : 0.f;

    for (int ci = 0; ci < Cin; ci++) {
        // stage current ci into smem
        #pragma unroll
        for (int k = 0; k < 5; k++) {
            int i = tid + k * 256;
            if (i < HALO) in_s[i] = hreg[k];
        }
        #pragma unroll
        for (int k = 0; k < 4; k++) {
            int idx = tid + k * 256;
            if (idx < WTOT) w_s2[idx] = make_float2(wreg[k], wreg[k]);
        }
        __syncthreads();

        // prefetch next ci while computing
        if (ci + 1 < Cin) {
            const float* inp = in + (size_t)(ci + 1) * VOX;
            #pragma unroll
            for (int k = 0; k < 5; k++) hreg[k] = hval[k] ? __ldg(inp + hoff[k]) : 0.f;
            const float* wp_ = w + (size_t)(ci + 1) * wstride;
            #pragma unroll
            for (int k = 0; k < 4; k++) wreg[k] = wvalid[k] ? __ldg(wp_ + wbase[k]) : 0.f;
        }

        const float2* wp = &w_s2[cg * 4 * 27];
        #pragma unroll
        for (int dz = 0; dz < 3; dz++) {
            #pragma unroll
            for (int dy = 0; dy < 3; dy++) {
                const float* row = &in_s[(dz * 10 + ty + dy) * 36 + tx * 8];
                float4 a4 = *(const float4*)row;
                float4 b4 = *(const float4*)(row + 4);
                float2 c2 = *(const float2*)(row + 8);
                float v[10] = {a4.x, a4.y, a4.z, a4.w, b4.x, b4.y, b4.z, b4.w, c2.x, c2.y};
                u64 p[9];
                #pragma unroll
                for (int i = 0; i < 9; i++) p[i] = pk2(v[i], v[i + 1]);
                const int tb = dz * 9 + dy * 3;
                #pragma unroll
                for (int co = 0; co < 4; co++) {
                    const float2* wc = wp + co * 27 + tb;
                    u64 w0 = *(const u64*)(wc + 0);
                    fma2(acc[co][0], p[0], w0); fma2(acc[co][1], p[2], w0);
                    fma2(acc[co][2], p[4], w0); fma2(acc[co][3], p[6], w0);
                    u64 w1 = *(const u64*)(wc + 1);
                    fma2(acc[co][0], p[1], w1); fma2(acc[co][1], p[3], w1);
                    fma2(acc[co][2], p[5], w1); fma2(acc[co][3], p[7], w1);
                    u64 w2 = *(const u64*)(wc + 2);
                    fma2(acc[co][0], p[2], w2); fma2(acc[co][1], p[4], w2);
                    fma2(acc[co][2], p[6], w2); fma2(acc[co][3], p[8], w2);
                }
            }
        }
        __syncthreads();
    }

    const int xo = x0 + tx * 8;
    const size_t base = (size_t)zb * HW + (y0 + ty) * W_ + xo;
    #pragma unroll
    for (int co = 0; co < 4; co++) {
        int coG = coBase + cg * 4 + co;
        if (coG < Cout) {
            float2 q0 = unpk2(acc[co][0]);
            float2 q1 = unpk2(acc[co][1]);
            float2 q2 = unpk2(acc[co][2]);
            float2 q3 = unpk2(acc[co][3]);
            float* op = out + (size_t)coG * VOX + base;
            *(float4*)(op + 0) = make_float4(q0.x, q0.y, q1.x, q1.y);
            *(float4*)(op + 4) = make_float4(q2.x, q2.y, q3.x, q3.y);
        }
    }
}

// ---------------------------------------------------------------------------
// si_sru: g has 4C channels [Wx | ft | rt | X]; activations fused.
// ---------------------------------------------------------------------------
__global__ void si_sru_k(const float* __restrict__ g, float* __restrict__ out,
                         const float* __restrict__ add, int C, int rev)
{
    int tid = blockIdx.x * blockDim.x + threadIdx.x;
    int total = C * HW;
    if (tid >= total) return;
    int c  = tid / HW;
    int yx = tid - c * HW;

    const float* Wp = g + (size_t)(0 * C + c) * VOX + yx;
    const float* Fp = g + (size_t)(1 * C + c) * VOX + yx;
    const float* Rp = g + (size_t)(2 * C + c) * VOX + yx;
    const float* Xp = g + (size_t)(3 * C + c) * VOX + yx;
    float*       op = out + (size_t)c * VOX + yx;
    const float* ap = add ? add + (size_t)c * VOX + yx : nullptr;

    int off = rev ? (D_ - 1) * HW : 0;
    int zs  = rev ? -HW : HW;

    float f = sigm(Fp[off]);
    float Cc = 1.f - f;
    float r = sigm(Rp[off]);
    float h = r * Cc + (1.f - r) * tanhf(Xp[off]);
    op[off] = h + (ap ? ap[off] : 0.f);

    for (int t = 1; t < D_; t++) {
        off += zs;
        f  = sigm(Fp[off]);
        Cc = f * Cc + (1.f - f) * tanhf(Wp[off]);
        r  = sigm(Rp[off]);
        h  = r * Cc + (1.f - r) * tanhf(Xp[off]);
        op[off] = h + (ap ? ap[off] : 0.f);
    }
}

// ---------------------------------------------------------------------------
// do_sru: g has 6C channels [Wx | ft | ft2 | rt | rt2 | X];
// ---------------------------------------------------------------------------
__global__ void do_sru_k(const float* __restrict__ g, float* __restrict__ out,
                         const float* __restrict__ add, int C)
{
    int tid = blockIdx.x * blockDim.x + threadIdx.x;
    int total = C * HW;
    if (tid >= total) return;
    int c  = tid / HW;
    int yx = tid - c * HW;

    const float* Wp = g + (size_t)(0 * C + c) * VOX + yx;
    const float* F1 = g + (size_t)(1 * C + c) * VOX + yx;
    const float* F2 = g + (size_t)(2 * C + c) * VOX + yx;
    const float* R1 = g + (size_t)(3 * C + c) * VOX + yx;
    const float* R2 = g + (size_t)(4 * C + c) * VOX + yx;
    const float* Xp = g + (size_t)(5 * C + c) * VOX + yx;
    float*       op = out + (size_t)c * VOX + yx;
    const float* ap = add ? add + (size_t)c * VOX + yx : nullptr;

    {
        float f = sigm(F1[0]);
        float Cc = 1.f - f;
        float r = sigm(R1[0]);
        op[0] = r * Cc + (1.f - r) * tanhf(Xp[0]);
        int off = 0;
        for (int t = 1; t < D_; t++) {
            off += HW;
            f  = sigm(F1[off]);
            Cc = f * Cc + (1.f - f) * tanhf(Wp[off]);
            r  = sigm(R1[off]);
            op[off] = r * Cc + (1.f - r) * tanhf(Xp[off]);
        }
    }
    {
        int off = (D_ - 1) * HW;
        float f = sigm(F2[off]);
        float Cc = 1.f - f;
        float r = sigm(R2[off]);
        float h = r * Cc + (1.f - r) * tanhf(Xp[off]);
        op[off] = op[off] + h + (ap ? ap[off] : 0.f);
        for (int t = 1; t < D_; t++) {
            off -= HW;
            f  = sigm(F2[off]);
            Cc = f * Cc + (1.f - f) * tanhf(Wp[off]);
            r  = sigm(R2[off]);
            h  = r * Cc + (1.f - r) * tanhf(Xp[off]);
            op[off] = op[off] + h + (ap ? ap[off] : 0.f);
        }
    }
}

// ---------------------------------------------------------------------------
static inline void conv_launch(const float* in, const float* w, float* out,
                               int Cin, int Cout, int deconv)
{
    dim3 grid(W_ / 32, (H_ / 8) * D_, (Cout + 31) / 32);
    conv3d_k<<<grid, 256>>>(in, w, out, Cin, Cout, deconv);
}

static inline void si_launch(const float* gbuf, float* out, const float* add,
                             int C, int rev)
{
    int n = C * HW;
    si_sru_k<<<(n + 255) / 256, 256>>>(gbuf, out, add, C, rev);
}

static inline void do_launch(const float* gbuf, float* out, const float* add, int C)
{
    int n = C * HW;
    do_sru_k<<<(n + 255) / 256, 256>>>(gbuf, out, add, C);
}

extern "C" void kernel_launch(void* const* d_in, const int* in_sizes, int n_in,
                              void* d_out, int out_size)
{
    (void)in_sizes; (void)n_in; (void)out_size;
    const float* x      = (const float*)d_in[0];
    const float* w_head = (const float*)d_in[1];
    const float* w_e0   = (const float*)d_in[2];
    const float* w_e1   = (const float*)d_in[3];
    const float* w_d0   = (const float*)d_in[4];
    const float* w_d1   = (const float*)d_in[5];
    const float* w_tail = (const float*)d_in[6];
    float* out = (float*)d_out;

    float *gc, *gh, *ge0, *ge1, *gd0, *gd1;
    cudaGetSymbolAddress((void**)&gc,  g_conv);
    cudaGetSymbolAddress((void**)&gh,  g_h);
    cudaGetSymbolAddress((void**)&ge0, g_e0);
    cudaGetSymbolAddress((void**)&ge1, g_e1);
    cudaGetSymbolAddress((void**)&gd0, g_d0);
    cudaGetSymbolAddress((void**)&gd1, g_d1);

    // h = do_sru(x, w_head)
    conv_launch(x, w_head, gc, 1, 96, 0);
    do_launch(gc, gh, nullptr, 16);
    // e0 = si_sru(h, w_e0, fwd)
    conv_launch(gh, w_e0, gc, 16, 128, 0);
    si_launch(gc, ge0, nullptr, 32, 0);
    // e1 = si_sru(e0, w_e1, rev)
    conv_launch(ge0, w_e1, gc, 32, 256, 0);
    si_launch(gc, ge1, nullptr, 64, 1);
    // d0 = si_sru(e1, w_d0, fwd, deconv) + e0
    conv_launch(ge1, w_d0, gc, 64, 128, 1);
    si_launch(gc, gd0, ge0, 32, 0);
    // d1 = si_sru(d0, w_d1, rev, deconv) + h
    conv_launch(gd0, w_d1, gc, 32, 64, 1);
    si_launch(gc, gd1, gh, 16, 1);
    // out = do_sru(d1, w_tail, deconv) + x
    conv_launch(gd1, w_tail, gc, 16, 6, 1);
    do_launch(gc, out, x, 1);
}

// round 6
// speedup vs baseline: 1.7011x; 1.0960x over previous
#include <cuda_runtime.h>
#include <cuda_bf16.h>
#include <math.h>
#include <stdint.h>

#define D_ 31
#define H_ 96
#define W_ 96
#define HW (H_*W_)        // 9216
#define VOX (D_*HW)       // 285696

// ---- scratch (device globals; no allocation allowed) ----
__device__ float g_conv[256 * VOX];
__device__ float g_h  [16 * VOX];
__device__ float g_e0 [32 * VOX];
__device__ float g_e1 [64 * VOX];
__device__ float g_d0 [32 * VOX];
__device__ float g_d1 [16 * VOX];
__device__ __nv_bfloat16 g_Ahi[262144];   // weights bf16-hi, [Mpad x Kpad]
__device__ __nv_bfloat16 g_Alo[262144];   // weights bf16-lo

__device__ __forceinline__ float sigm(float a) { return 1.0f / (1.0f + expf(-a)); }

typedef unsigned long long u64;
__device__ __forceinline__ void fma2(u64& d, u64 a, u64 b) {
    asm("fma.rn.f32x2 %0, %1, %2, %0;" : "+l"(d) : "l"(a), "l"(b));
}
__device__ __forceinline__ u64 pk2(float x, float y) {
    u64 r; asm("mov.b64 %0, {%1, %2};" : "=l"(r) : "f"(x), "f"(y)); return r;
}
__device__ __forceinline__ float2 unpk2(u64 a) {
    float x, y; asm("mov.b64 {%0, %1}, %2;" : "=f"(x), "=f"(y) : "l"(a));
    return make_float2(x, y);
}

// ============================================================================
// Weight prep: split fp32 weights into bf16 hi/lo, layout A[m][k], k=ci*32+t.
// deconv=1: W_eff[m][ci][t] = w[ci][m][26-t]
// ============================================================================
__global__ void prep_k(const float* __restrict__ w, __nv_bfloat16* __restrict__ Ahi,
                       __nv_bfloat16* __restrict__ Alo,
                       int Cin, int Cout, int Kpad, int deconv, int total)
{
    int i = blockIdx.x * 256 + threadIdx.x;
    if (i >= total) return;
    int m = i / Kpad, k = i - m * Kpad;
    int t = k & 31, ci = k >> 5;
    float v = 0.f;
    if (t < 27 && m < Cout && ci < Cin)
        v = deconv ? w[((size_t)ci * Cout + m) * 27 + (26 - t)]
                   : w[((size_t)m * Cin + ci) * 27 + t];
    __nv_bfloat16 h = __float2bfloat16(v);
    Ahi[i] = h;
    Alo[i] = __float2bfloat16(v - __bfloat162float(h));
}

// ============================================================================
// Tensor-core implicit-GEMM conv (HMMA mma.sync m16n8k16 bf16, hi/lo split).
// Block 256 thr = 8 warps (2 M-rows x 4 N-cols). Block tile: M=64 co, N=96 x.
// Grid: (z*96+y, Cout/64). K = Cin*32 (27 taps padded), chunks of 16.
// ============================================================================
__device__ __forceinline__ void mma16816(float* c, const uint32_t* a, const uint32_t* b) {
    asm volatile("mma.sync.aligned.m16n8k16.row.col.f32.bf16.bf16.f32 "
                 "{%0,%1,%2,%3},{%4,%5,%6,%7},{%8,%9},{%0,%1,%2,%3};"
                 : "+f"(c[0]), "+f"(c[1]), "+f"(c[2]), "+f"(c[3])
                 : "r"(a[0]), "r"(a[1]), "r"(a[2]), "r"(a[3]), "r"(b[0]), "r"(b[1]));
}

__global__ __launch_bounds__(256)
void conv_mma_k(const float* __restrict__ in,
                const __nv_bfloat16* __restrict__ Ahi,
                const __nv_bfloat16* __restrict__ Alo,
                float* __restrict__ out,
                int Cin, int Kpad, int NC2)
{
    __shared__ __align__(16) __nv_bfloat16 AsH[2][64*16], AsL[2][64*16];
    __shared__ __align__(16) __nv_bfloat16 BsH[2][96*16], BsL[2][96*16];

    const int tid  = threadIdx.x;
    const int wid  = tid >> 5, lane = tid & 31;
    const int g    = lane >> 2, t4 = lane & 3;
    const int bx   = blockIdx.x, mb = blockIdx.y;
    const int z    = bx / 96, y = bx - z * 96;

    const int kloc   = tid & 15;       // k within chunk (fixed per thread)
    const int nmbase = tid >> 4;       // base row for staging (0..15)

    const int m0 = (wid >> 2) * 32;    // warp M offset
    const int n0 = (wid & 3) * 24;     // warp N offset

    float acc[2][3][4];
    #pragma unroll
    for (int mt = 0; mt < 2; mt++)
        #pragma unroll
        for (int nt = 0; nt < 3; nt++)
            #pragma unroll
            for (int j = 0; j < 4; j++) acc[mt][nt][j] = 0.f;

    // ---- staging registers ----
    float bv[6];
    __nv_bfloat16 avh[4], avl[4];

    // loader: chunk c -> regs
    auto loadRegs = [&](int c) {
        const int ci = c >> 1, t0 = (c & 1) * 16;
        const int t = t0 + kloc;
        int dz = t / 9, r9 = t - dz * 9;
        int dy = r9 / 3, dx = r9 - dy * 3;
        int zz = z + dz - 1, gy = y + dy - 1;
        bool rowok = (t < 27) && ((unsigned)zz < D_) && ((unsigned)gy < H_);
        const float* rp = in + (size_t)ci * VOX + (size_t)zz * HW + gy * 96 + dx - 1;
        #pragma unroll
        for (int r = 0; r < 6; r++) {
            int n = nmbase + r * 16;
            int gx = n + dx - 1;
            bv[r] = (rowok && (unsigned)gx < W_) ? __ldg(rp + n) : 0.f;
        }
        const size_t abase = (size_t)(mb * 64 + nmbase) * Kpad + c * 16 + kloc;
        #pragma unroll
        for (int r = 0; r < 4; r++) {
            avh[r] = Ahi[abase + (size_t)r * 16 * Kpad];
            avl[r] = Alo[abase + (size_t)r * 16 * Kpad];
        }
    };
    // storer: regs -> stage st
    auto storeRegs = [&](int st) {
        #pragma unroll
        for (int r = 0; r < 6; r++) {
            int n = nmbase + r * 16;
            float v = bv[r];
            __nv_bfloat16 h = __float2bfloat16(v);
            BsH[st][n * 16 + kloc] = h;
            BsL[st][n * 16 + kloc] = __float2bfloat16(v - __bfloat162float(h));
        }
        #pragma unroll
        for (int r = 0; r < 4; r++) {
            int m = nmbase + r * 16;
            AsH[st][m * 16 + kloc] = avh[r];
            AsL[st][m * 16 + kloc] = avl[r];
        }
    };

    loadRegs(0);
    storeRegs(0);
    __syncthreads();

    for (int c = 0; c < NC2; c++) {
        const int st = c & 1;
        const bool more = (c + 1 < NC2);
        if (more) loadRegs(c + 1);

        const uint32_t* AH = (const uint32_t*)AsH[st];
        const uint32_t* AL = (const uint32_t*)AsL[st];
        const uint32_t* BH = (const uint32_t*)BsH[st];
        const uint32_t* BL = (const uint32_t*)BsL[st];

        uint32_t ah[2][4], al[2][4], bh[3][2], bl[3][2];
        #pragma unroll
        for (int mt = 0; mt < 2; mt++) {
            int mr = m0 + mt * 16;
            ah[mt][0] = AH[(mr + g) * 8 + t4];
            ah[mt][1] = AH[(mr + g + 8) * 8 + t4];
            ah[mt][2] = AH[(mr + g) * 8 + t4 + 4];
            ah[mt][3] = AH[(mr + g + 8) * 8 + t4 + 4];
            al[mt][0] = AL[(mr + g) * 8 + t4];
            al[mt][1] = AL[(mr + g + 8) * 8 + t4];
            al[mt][2] = AL[(mr + g) * 8 + t4 + 4];
            al[mt][3] = AL[(mr + g + 8) * 8 + t4 + 4];
        }
        #pragma unroll
        for (int nt = 0; nt < 3; nt++) {
            int nn = n0 + nt * 8 + g;
            bh[nt][0] = BH[nn * 8 + t4];
            bh[nt][1] = BH[nn * 8 + t4 + 4];
            bl[nt][0] = BL[nn * 8 + t4];
            bl[nt][1] = BL[nn * 8 + t4 + 4];
        }
        #pragma unroll
        for (int mt = 0; mt < 2; mt++)
            #pragma unroll
            for (int nt = 0; nt < 3; nt++) {
                mma16816(acc[mt][nt], ah[mt], bh[nt]);
                mma16816(acc[mt][nt], ah[mt], bl[nt]);
                mma16816(acc[mt][nt], al[mt], bh[nt]);
            }

        if (more) storeRegs(1 - st);
        __syncthreads();
    }

    // epilogue: Cout is a multiple of 64 for all mma layers -> no mask needed
    const size_t zy = (size_t)z * HW + y * 96;
    #pragma unroll
    for (int mt = 0; mt < 2; mt++) {
        int co = mb * 64 + m0 + mt * 16 + g;
        #pragma unroll
        for (int nt = 0; nt < 3; nt++) {
            int n = n0 + nt * 8 + t4 * 2;
            float* op = out + (size_t)co * VOX + zy + n;
            *(float2*)op = make_float2(acc[mt][nt][0], acc[mt][nt][1]);
            *(float2*)(op + (size_t)8 * VOX) = make_float2(acc[mt][nt][2], acc[mt][nt][3]);
        }
    }
}

// ============================================================================
// Scalar FFMA2 conv (kept for head Cin=1 and tail Cout=6 layers).
// ============================================================================
#define HALO 1080
#define WTOT 864

__global__ __launch_bounds__(256, 2)
void conv3d_k(const float* __restrict__ in, const float* __restrict__ w,
              float* __restrict__ out, int Cin, int Cout, int deconv)
{
    __shared__ __align__(16) float  in_s[HALO];
    __shared__ __align__(8)  float2 w_s2[WTOT];

    const int tid = threadIdx.x;
    const int tx  = tid & 3;
    const int ty  = (tid >> 2) & 7;
    const int cg  = tid >> 5;

    const int x0 = blockIdx.x * 32;
    const int y0 = (blockIdx.y % 12) * 8;
    const int zb = blockIdx.y / 12;
    const int coBase = blockIdx.z * 32;

    int  hoff[5]; bool hval[5];
    #pragma unroll
    for (int k = 0; k < 5; k++) {
        int i = tid + k * 256;
        if (i < HALO) {
            int dz  = i / 360;
            int rem = i - dz * 360;
            int yy  = rem / 36;
            int xx  = rem - yy * 36;
            int z = zb + dz - 1, y = y0 + yy - 1, x = x0 + xx - 1;
            hval[k] = ((unsigned)z < D_) && ((unsigned)y < H_) && ((unsigned)x < W_) && (xx < 34);
            hoff[k] = z * HW + y * W_ + x;
        } else { hval[k] = false; hoff[k] = 0; }
    }
    int wbase[4]; bool wvalid[4];
    const int wstride = deconv ? Cout * 27 : 27;
    #pragma unroll
    for (int k = 0; k < 4; k++) {
        int idx = tid + k * 256;
        if (idx < WTOT) {
            int co = idx / 27, t = idx - co * 27;
            int coG = coBase + co;
            wvalid[k] = (coG < Cout);
            wbase[k]  = deconv ? (coG * 27 + (26 - t)) : (coG * Cin * 27 + t);
        } else { wvalid[k] = false; wbase[k] = 0; }
    }

    u64 acc[4][4];
    #pragma unroll
    for (int c = 0; c < 4; c++)
        #pragma unroll
        for (int j = 0; j < 4; j++) acc[c][j] = 0ull;

    float hreg[5], wreg[4];
    #pragma unroll
    for (int k = 0; k < 5; k++) hreg[k] = hval[k] ? __ldg(in + hoff[k]) : 0.f;
    #pragma unroll
    for (int k = 0; k < 4; k++) wreg[k] = wvalid[k] ? __ldg(w + wbase[k]) : 0.f;

    for (int ci = 0; ci < Cin; ci++) {
        #pragma unroll
        for (int k = 0; k < 5; k++) {
            int i = tid + k * 256;
            if (i < HALO) in_s[i] = hreg[k];
        }
        #pragma unroll
        for (int k = 0; k < 4; k++) {
            int idx = tid + k * 256;
            if (idx < WTOT) w_s2[idx] = make_float2(wreg[k], wreg[k]);
        }
        __syncthreads();

        if (ci + 1 < Cin) {
            const float* inp = in + (size_t)(ci + 1) * VOX;
            #pragma unroll
            for (int k = 0; k < 5; k++) hreg[k] = hval[k] ? __ldg(inp + hoff[k]) : 0.f;
            const float* wp_ = w + (size_t)(ci + 1) * wstride;
            #pragma unroll
            for (int k = 0; k < 4; k++) wreg[k] = wvalid[k] ? __ldg(wp_ + wbase[k]) : 0.f;
        }

        const float2* wp = &w_s2[cg * 4 * 27];
        #pragma unroll
        for (int dz = 0; dz < 3; dz++) {
            #pragma unroll
            for (int dy = 0; dy < 3; dy++) {
                const float* row = &in_s[(dz * 10 + ty + dy) * 36 + tx * 8];
                float4 a4 = *(const float4*)row;
                float4 b4 = *(const float4*)(row + 4);
                float2 c2 = *(const float2*)(row + 8);
                float v[10] = {a4.x, a4.y, a4.z, a4.w, b4.x, b4.y, b4.z, b4.w, c2.x, c2.y};
                u64 p[9];
                #pragma unroll
                for (int i = 0; i < 9; i++) p[i] = pk2(v[i], v[i + 1]);
                const int tb = dz * 9 + dy * 3;
                #pragma unroll
                for (int co = 0; co < 4; co++) {
                    const float2* wc = wp + co * 27 + tb;
                    u64 w0 = *(const u64*)(wc + 0);
                    fma2(acc[co][0], p[0], w0); fma2(acc[co][1], p[2], w0);
                    fma2(acc[co][2], p[4], w0); fma2(acc[co][3], p[6], w0);
                    u64 w1 = *(const u64*)(wc + 1);
                    fma2(acc[co][0], p[1], w1); fma2(acc[co][1], p[3], w1);
                    fma2(acc[co][2], p[5], w1); fma2(acc[co][3], p[7], w1);
                    u64 w2 = *(const u64*)(wc + 2);
                    fma2(acc[co][0], p[2], w2); fma2(acc[co][1], p[4], w2);
                    fma2(acc[co][2], p[6], w2); fma2(acc[co][3], p[8], w2);
                }
            }
        }
        __syncthreads();
    }

    const int xo = x0 + tx * 8;
    const size_t base = (size_t)zb * HW + (y0 + ty) * W_ + xo;
    #pragma unroll
    for (int co = 0; co < 4; co++) {
        int coG = coBase + cg * 4 + co;
        if (coG < Cout) {
            float2 q0 = unpk2(acc[co][0]);
            float2 q1 = unpk2(acc[co][1]);
            float2 q2 = unpk2(acc[co][2]);
            float2 q3 = unpk2(acc[co][3]);
            float* op = out + (size_t)coG * VOX + base;
            *(float4*)(op + 0) = make_float4(q0.x, q0.y, q1.x, q1.y);
            *(float4*)(op + 4) = make_float4(q2.x, q2.y, q3.x, q3.y);
        }
    }
}

// ============================ SRU kernels ============================
__global__ void si_sru_k(const float* __restrict__ g, float* __restrict__ out,
                         const float* __restrict__ add, int C, int rev)
{
    int tid = blockIdx.x * blockDim.x + threadIdx.x;
    int total = C * HW;
    if (tid >= total) return;
    int c  = tid / HW;
    int yx = tid - c * HW;

    const float* Wp = g + (size_t)(0 * C + c) * VOX + yx;
    const float* Fp = g + (size_t)(1 * C + c) * VOX + yx;
    const float* Rp = g + (size_t)(2 * C + c) * VOX + yx;
    const float* Xp = g + (size_t)(3 * C + c) * VOX + yx;
    float*       op = out + (size_t)c * VOX + yx;
    const float* ap = add ? add + (size_t)c * VOX + yx : nullptr;

    int off = rev ? (D_ - 1) * HW : 0;
    int zs  = rev ? -HW : HW;

    float f = sigm(Fp[off]);
    float Cc = 1.f - f;
    float r = sigm(Rp[off]);
    float h = r * Cc + (1.f - r) * tanhf(Xp[off]);
    op[off] = h + (ap ? ap[off] : 0.f);

    for (int t = 1; t < D_; t++) {
        off += zs;
        f  = sigm(Fp[off]);
        Cc = f * Cc + (1.f - f) * tanhf(Wp[off]);
        r  = sigm(Rp[off]);
        h  = r * Cc + (1.f - r) * tanhf(Xp[off]);
        op[off] = h + (ap ? ap[off] : 0.f);
    }
}

__global__ void do_sru_k(const float* __restrict__ g, float* __restrict__ out,
                         const float* __restrict__ add, int C)
{
    int tid = blockIdx.x * blockDim.x + threadIdx.x;
    int total = C * HW;
    if (tid >= total) return;
    int c  = tid / HW;
    int yx = tid - c * HW;

    const float* Wp = g + (size_t)(0 * C + c) * VOX + yx;
    const float* F1 = g + (size_t)(1 * C + c) * VOX + yx;
    const float* F2 = g + (size_t)(2 * C + c) * VOX + yx;
    const float* R1 = g + (size_t)(3 * C + c) * VOX + yx;
    const float* R2 = g + (size_t)(4 * C + c) * VOX + yx;
    const float* Xp = g + (size_t)(5 * C + c) * VOX + yx;
    float*       op = out + (size_t)c * VOX + yx;
    const float* ap = add ? add + (size_t)c * VOX + yx : nullptr;

    {
        float f = sigm(F1[0]);
        float Cc = 1.f - f;
        float r = sigm(R1[0]);
        op[0] = r * Cc + (1.f - r) * tanhf(Xp[0]);
        int off = 0;
        for (int t = 1; t < D_; t++) {
            off += HW;
            f  = sigm(F1[off]);
            Cc = f * Cc + (1.f - f) * tanhf(Wp[off]);
            r  = sigm(R1[off]);
            op[off] = r * Cc + (1.f - r) * tanhf(Xp[off]);
        }
    }
    {
        int off = (D_ - 1) * HW;
        float f = sigm(F2[off]);
        float Cc = 1.f - f;
        float r = sigm(R2[off]);
        float h = r * Cc + (1.f - r) * tanhf(Xp[off]);
        op[off] = op[off] + h + (ap ? ap[off] : 0.f);
        for (int t = 1; t < D_; t++) {
            off -= HW;
            f  = sigm(F2[off]);
            Cc = f * Cc + (1.f - f) * tanhf(Wp[off]);
            r  = sigm(R2[off]);
            h  = r * Cc + (1.f - r) * tanhf(Xp[off]);
            op[off] = op[off] + h + (ap ? ap[off] : 0.f);
        }
    }
}

// ============================ host ============================
static __nv_bfloat16 *s_Ahi, *s_Alo;

static inline void conv_tc(const float* in, const float* w, float* out,
                           int Cin, int Cout, int deconv)
{
    int Kpad = Cin * 32;
    int total = Cout * Kpad;
    prep_k<<<(total + 255) / 256, 256>>>(w, s_Ahi, s_Alo, Cin, Cout, Kpad, deconv, total);
    dim3 grid(D_ * 96, Cout / 64);
    conv_mma_k<<<grid, 256>>>(in, s_Ahi, s_Alo, out, Cin, Kpad, Cin * 2);
}

static inline void conv_scalar(const float* in, const float* w, float* out,
                               int Cin, int Cout, int deconv)
{
    dim3 grid(W_ / 32, (H_ / 8) * D_, (Cout + 31) / 32);
    conv3d_k<<<grid, 256>>>(in, w, out, Cin, Cout, deconv);
}

static inline void si_launch(const float* gbuf, float* out, const float* add, int C, int rev)
{
    int n = C * HW;
    si_sru_k<<<(n + 255) / 256, 256>>>(gbuf, out, add, C, rev);
}
static inline void do_launch(const float* gbuf, float* out, const float* add, int C)
{
    int n = C * HW;
    do_sru_k<<<(n + 255) / 256, 256>>>(gbuf, out, add, C);
}

extern "C" void kernel_launch(void* const* d_in, const int* in_sizes, int n_in,
                              void* d_out, int out_size)
{
    (void)in_sizes; (void)n_in; (void)out_size;
    const float* x      = (const float*)d_in[0];
    const float* w_head = (const float*)d_in[1];
    const float* w_e0   = (const float*)d_in[2];
    const float* w_e1   = (const float*)d_in[3];
    const float* w_d0   = (const float*)d_in[4];
    const float* w_d1   = (const float*)d_in[5];
    const float* w_tail = (const float*)d_in[6];
    float* out = (float*)d_out;

    float *gc, *gh, *ge0, *ge1, *gd0, *gd1;
    cudaGetSymbolAddress((void**)&gc,  g_conv);
    cudaGetSymbolAddress((void**)&gh,  g_h);
    cudaGetSymbolAddress((void**)&ge0, g_e0);
    cudaGetSymbolAddress((void**)&ge1, g_e1);
    cudaGetSymbolAddress((void**)&gd0, g_d0);
    cudaGetSymbolAddress((void**)&gd1, g_d1);
    cudaGetSymbolAddress((void**)&s_Ahi, g_Ahi);
    cudaGetSymbolAddress((void**)&s_Alo, g_Alo);

    // h = do_sru(x, w_head)          (scalar: Cin=1)
    conv_scalar(x, w_head, gc, 1, 96, 0);
    do_launch(gc, gh, nullptr, 16);
    // e0 = si_sru(h, w_e0, fwd)      (mma: 16 -> 128)
    conv_tc(gh, w_e0, gc, 16, 128, 0);
    si_launch(gc, ge0, nullptr, 32, 0);
    // e1 = si_sru(e0, w_e1, rev)     (mma: 32 -> 256)
    conv_tc(ge0, w_e1, gc, 32, 256, 0);
    si_launch(gc, ge1, nullptr, 64, 1);
    // d0 = si_sru(e1, w_d0, fwd, deconv) + e0   (mma: 64 -> 128)
    conv_tc(ge1, w_d0, gc, 64, 128, 1);
    si_launch(gc, gd0, ge0, 32, 0);
    // d1 = si_sru(d0, w_d1, rev, deconv) + h    (mma: 32 -> 64)
    conv_tc(gd0, w_d1, gc, 32, 64, 1);
    si_launch(gc, gd1, gh, 16, 1);
    // out = do_sru(d1, w_tail, deconv) + x      (scalar: Cout=6)
    conv_scalar(gd1, w_tail, gc, 16, 6, 1);
    do_launch(gc, out, x, 1);
}

// round 7
// speedup vs baseline: 2.3048x; 1.3549x over previous
#include <cuda_runtime.h>
#include <cuda_bf16.h>
#include <math.h>
#include <stdint.h>

#define D_ 31
#define H_ 96
#define W_ 96
#define HW (H_*W_)        // 9216
#define VOX (D_*HW)       // 285696

// ---- scratch (device globals; no allocation allowed) ----
__device__ float g_conv[256 * VOX];
__device__ float g_h  [16 * VOX];
__device__ float g_e0 [32 * VOX];
__device__ float g_e1 [64 * VOX];
__device__ float g_d0 [32 * VOX];
__device__ float g_d1 [16 * VOX];
__device__ __nv_bfloat16 g_Ahi[262144];   // weights bf16-hi, [M x Kpad]
__device__ __nv_bfloat16 g_Alo[262144];   // weights bf16-lo

__device__ __forceinline__ float sigm(float a) { return 1.0f / (1.0f + expf(-a)); }

typedef unsigned long long u64;
__device__ __forceinline__ void fma2(u64& d, u64 a, u64 b) {
    asm("fma.rn.f32x2 %0, %1, %2, %0;" : "+l"(d) : "l"(a), "l"(b));
}
__device__ __forceinline__ u64 pk2(float x, float y) {
    u64 r; asm("mov.b64 %0, {%1, %2};" : "=l"(r) : "f"(x), "f"(y)); return r;
}
__device__ __forceinline__ float2 unpk2(u64 a) {
    float x, y; asm("mov.b64 {%0, %1}, %2;" : "=f"(x), "=f"(y) : "l"(a));
    return make_float2(x, y);
}
__device__ __forceinline__ uint32_t smem_u32(const void* p) {
    uint32_t a;
    asm("{ .reg .u64 t; cvta.to.shared.u64 t, %1; cvt.u32.u64 %0, t; }" : "=r"(a) : "l"(p));
    return a;
}
__device__ __forceinline__ void ldsm4(uint32_t* r, uint32_t addr) {
    asm volatile("ldmatrix.sync.aligned.m8n8.x4.shared.b16 {%0,%1,%2,%3}, [%4];"
                 : "=r"(r[0]), "=r"(r[1]), "=r"(r[2]), "=r"(r[3]) : "r"(addr));
}
__device__ __forceinline__ void ldsm2(uint32_t* r, uint32_t addr) {
    asm volatile("ldmatrix.sync.aligned.m8n8.x2.shared.b16 {%0,%1}, [%2];"
                 : "=r"(r[0]), "=r"(r[1]) : "r"(addr));
}
__device__ __forceinline__ void mma16816(float* c, const uint32_t* a, const uint32_t* b) {
    asm volatile("mma.sync.aligned.m16n8k16.row.col.f32.bf16.bf16.f32 "
                 "{%0,%1,%2,%3},{%4,%5,%6,%7},{%8,%9},{%0,%1,%2,%3};"
                 : "+f"(c[0]), "+f"(c[1]), "+f"(c[2]), "+f"(c[3])
                 : "r"(a[0]), "r"(a[1]), "r"(a[2]), "r"(a[3]), "r"(b[0]), "r"(b[1]));
}
__device__ __forceinline__ uint32_t pkbf2(float x, float y) {
    __nv_bfloat162 p = __floats2bfloat162_rn(x, y);
    return *(uint32_t*)&p;
}

// ============================================================================
// Weight prep: split fp32 weights into bf16 hi/lo, layout A[m][k], k=ci*32+t.
// ============================================================================
__global__ void prep_k(const float* __restrict__ w, __nv_bfloat16* __restrict__ Ahi,
                       __nv_bfloat16* __restrict__ Alo,
                       int Cin, int Cout, int Kpad, int deconv, int total)
{
    int i = blockIdx.x * 256 + threadIdx.x;
    if (i >= total) return;
    int m = i / Kpad, k = i - m * Kpad;
    int t = k & 31, ci = k >> 5;
    float v = 0.f;
    if (t < 27 && m < Cout && ci < Cin)
        v = deconv ? w[((size_t)ci * Cout + m) * 27 + (26 - t)]
                   : w[((size_t)m * Cin + ci) * 27 + t];
    __nv_bfloat16 h = __float2bfloat16(v);
    Ahi[i] = h;
    Alo[i] = __float2bfloat16(v - __bfloat162float(h));
}

// ============================================================================
// Tensor-core implicit-GEMM conv (mma.sync m16n8k16 bf16 hi/lo, ldmatrix).
// Block 256 thr = 8 warps (2 M x 4 N). Tile: M=64 co, N=96 x. K chunks of 16.
// Smem stride padded to 24 bf16 (48B) -> conflict-free LDSM & STS.
// ============================================================================
#define KS 24               // padded k stride (elems)
#define AS_E (64*KS)        // 1536 elems, 3072 B per stage
#define BS_E (96*KS)        // 2304 elems, 4608 B per stage

__global__ __launch_bounds__(256)
void conv_mma_k(const float* __restrict__ in,
                const __nv_bfloat16* __restrict__ Ahi,
                const __nv_bfloat16* __restrict__ Alo,
                float* __restrict__ out,
                int Cin, int Kpad, int NC2)
{
    __shared__ __align__(16) __nv_bfloat16 AsH[2][AS_E], AsL[2][AS_E];
    __shared__ __align__(16) __nv_bfloat16 BsH[2][BS_E], BsL[2][BS_E];

    const int tid  = threadIdx.x;
    const int wid  = tid >> 5, lane = tid & 31;
    const int g    = lane >> 2, t4 = lane & 3;
    const int bx   = blockIdx.x, mb = blockIdx.y;
    const int z    = bx / 96, y = bx - z * 96;

    const int kp = tid & 7;            // k-pair (k = 2kp, 2kp+1)
    const int rb = tid >> 3;           // staging row base (0..31)

    const int m0 = (wid >> 2) * 32;    // warp M offset
    const int n0 = (wid & 3) * 24;     // warp N offset

    // fragment lane byte-offsets (within a stage)
    const uint32_t offA  = (uint32_t)(((lane & 7) + ((lane >> 3) & 1) * 8) * KS + (lane >> 4) * 8) * 2;
    const uint32_t offB1 = (uint32_t)((n0 + ((lane >> 4) << 3) + (lane & 7)) * KS + ((lane >> 3) & 1) * 8) * 2;
    const uint32_t offB2 = (uint32_t)((n0 + 16 + (lane & 7)) * KS + ((lane >> 3) & 1) * 8) * 2;

    const uint32_t baAH = smem_u32(AsH), baAL = smem_u32(AsL);
    const uint32_t baBH = smem_u32(BsH), baBL = smem_u32(BsL);

    float acc[2][3][4];
    #pragma unroll
    for (int mt = 0; mt < 2; mt++)
        #pragma unroll
        for (int nt = 0; nt < 3; nt++)
            #pragma unroll
            for (int j = 0; j < 4; j++) acc[mt][nt][j] = 0.f;

    // ---- staging registers ----
    float bv[3][2];
    uint32_t avh[2], avl[2];

    auto loadRegs = [&](int c) {
        const int ci = c >> 1, t0 = (c & 1) * 16;
        #pragma unroll
        for (int kk = 0; kk < 2; kk++) {
            int t = t0 + 2 * kp + kk;
            int dz = t / 9, r9 = t - dz * 9;
            int dy = r9 / 3, dx = r9 - dy * 3;
            int zz = z + dz - 1, gy = y + dy - 1;
            bool rowok = (t < 27) && ((unsigned)zz < D_) && ((unsigned)gy < H_);
            const float* rp = in + (size_t)ci * VOX + (size_t)zz * HW + gy * 96 + dx - 1;
            #pragma unroll
            for (int r = 0; r < 3; r++) {
                int n = rb + r * 32;
                int gx = n + dx - 1;
                bv[r][kk] = (rowok && (unsigned)gx < W_) ? __ldg(rp + n) : 0.f;
            }
        }
        const size_t ab = (size_t)(mb * 64 + rb) * Kpad + c * 16 + 2 * kp;
        avh[0] = *(const uint32_t*)(Ahi + ab);
        avh[1] = *(const uint32_t*)(Ahi + ab + (size_t)32 * Kpad);
        avl[0] = *(const uint32_t*)(Alo + ab);
        avl[1] = *(const uint32_t*)(Alo + ab + (size_t)32 * Kpad);
    };
    auto storeRegs = [&](int st) {
        #pragma unroll
        for (int r = 0; r < 3; r++) {
            int n = rb + r * 32;
            float v0 = bv[r][0], v1 = bv[r][1];
            __nv_bfloat16 h0 = __float2bfloat16(v0), h1 = __float2bfloat16(v1);
            *(uint32_t*)&BsH[st][n * KS + 2 * kp] = pkbf2(v0, v1) /*rn pair*/;
            // lo residuals must match the hi actually stored: recompute via rn pair
            __nv_bfloat162 hp = __floats2bfloat162_rn(v0, v1);
            float l0 = v0 - __bfloat162float(hp.x);
            float l1 = v1 - __bfloat162float(hp.y);
            *(uint32_t*)&BsL[st][n * KS + 2 * kp] = pkbf2(l0, l1);
            (void)h0; (void)h1;
        }
        #pragma unroll
        for (int r = 0; r < 2; r++) {
            int m = rb + r * 32;
            *(uint32_t*)&AsH[st][m * KS + 2 * kp] = avh[r];
            *(uint32_t*)&AsL[st][m * KS + 2 * kp] = avl[r];
        }
    };

    loadRegs(0);
    storeRegs(0);
    __syncthreads();

    for (int c = 0; c < NC2; c++) {
        const int st = c & 1;
        const bool more = (c + 1 < NC2);
        if (more) loadRegs(c + 1);

        const uint32_t sa = st * (AS_E * 2);   // stage byte offsets
        const uint32_t sb = st * (BS_E * 2);

        uint32_t ah0[4], ah1[4], al0[4], al1[4], bh[6], bl[6];
        ldsm4(ah0, baAH + sa + m0 * (KS*2) + offA);
        ldsm4(ah1, baAH + sa + (m0 + 16) * (KS*2) + offA);
        ldsm4(al0, baAL + sa + m0 * (KS*2) + offA);
        ldsm4(al1, baAL + sa + (m0 + 16) * (KS*2) + offA);
        ldsm4(bh,     baBH + sb + offB1);
        ldsm2(bh + 4, baBH + sb + offB2);
        ldsm4(bl,     baBL + sb + offB1);
        ldsm2(bl + 4, baBL + sb + offB2);

        #pragma unroll
        for (int mt = 0; mt < 2; mt++) {
            const uint32_t* ahp = mt ? ah1 : ah0;
            const uint32_t* alp = mt ? al1 : al0;
            #pragma unroll
            for (int nt = 0; nt < 3; nt++) {
                mma16816(acc[mt][nt], ahp, &bh[nt * 2]);
                mma16816(acc[mt][nt], ahp, &bl[nt * 2]);
                mma16816(acc[mt][nt], alp, &bh[nt * 2]);
            }
        }

        if (more) storeRegs(1 - st);
        __syncthreads();
    }

    // epilogue: Cout multiple of 64 for all mma layers
    const size_t zy = (size_t)z * HW + y * 96;
    #pragma unroll
    for (int mt = 0; mt < 2; mt++) {
        int co = mb * 64 + m0 + mt * 16 + g;
        #pragma unroll
        for (int nt = 0; nt < 3; nt++) {
            int n = n0 + nt * 8 + t4 * 2;
            float* op = out + (size_t)co * VOX + zy + n;
            *(float2*)op = make_float2(acc[mt][nt][0], acc[mt][nt][1]);
            *(float2*)(op + (size_t)8 * VOX) = make_float2(acc[mt][nt][2], acc[mt][nt][3]);
        }
    }
}

// ============================================================================
// Scalar FFMA2 conv (head Cin=1 and tail Cout=6 layers).
// ============================================================================
#define HALO 1080
#define WTOT 864

__global__ __launch_bounds__(256, 2)
void conv3d_k(const float* __restrict__ in, const float* __restrict__ w,
              float* __restrict__ out, int Cin, int Cout, int deconv)
{
    __shared__ __align__(16) float  in_s[HALO];
    __shared__ __align__(8)  float2 w_s2[WTOT];

    const int tid = threadIdx.x;
    const int tx  = tid & 3;
    const int ty  = (tid >> 2) & 7;
    const int cg  = tid >> 5;

    const int x0 = blockIdx.x * 32;
    const int y0 = (blockIdx.y % 12) * 8;
    const int zb = blockIdx.y / 12;
    const int coBase = blockIdx.z * 32;

    int  hoff[5]; bool hval[5];
    #pragma unroll
    for (int k = 0; k < 5; k++) {
        int i = tid + k * 256;
        if (i < HALO) {
            int dz  = i / 360;
            int rem = i - dz * 360;
            int yy  = rem / 36;
            int xx  = rem - yy * 36;
            int z = zb + dz - 1, y = y0 + yy - 1, x = x0 + xx - 1;
            hval[k] = ((unsigned)z < D_) && ((unsigned)y < H_) && ((unsigned)x < W_) && (xx < 34);
            hoff[k] = z * HW + y * W_ + x;
        } else { hval[k] = false; hoff[k] = 0; }
    }
    int wbase[4]; bool wvalid[4];
    const int wstride = deconv ? Cout * 27 : 27;
    #pragma unroll
    for (int k = 0; k < 4; k++) {
        int idx = tid + k * 256;
        if (idx < WTOT) {
            int co = idx / 27, t = idx - co * 27;
            int coG = coBase + co;
            wvalid[k] = (coG < Cout);
            wbase[k]  = deconv ? (coG * 27 + (26 - t)) : (coG * Cin * 27 + t);
        } else { wvalid[k] = false; wbase[k] = 0; }
    }

    u64 acc[4][4];
    #pragma unroll
    for (int c = 0; c < 4; c++)
        #pragma unroll
        for (int j = 0; j < 4; j++) acc[c][j] = 0ull;

    float hreg[5], wreg[4];
    #pragma unroll
    for (int k = 0; k < 5; k++) hreg[k] = hval[k] ? __ldg(in + hoff[k]) : 0.f;
    #pragma unroll
    for (int k = 0; k < 4; k++) wreg[k] = wvalid[k] ? __ldg(w + wbase[k]) : 0.f;

    for (int ci = 0; ci < Cin; ci++) {
        #pragma unroll
        for (int k = 0; k < 5; k++) {
            int i = tid + k * 256;
            if (i < HALO) in_s[i] = hreg[k];
        }
        #pragma unroll
        for (int k = 0; k < 4; k++) {
            int idx = tid + k * 256;
            if (idx < WTOT) w_s2[idx] = make_float2(wreg[k], wreg[k]);
        }
        __syncthreads();

        if (ci + 1 < Cin) {
            const float* inp = in + (size_t)(ci + 1) * VOX;
            #pragma unroll
            for (int k = 0; k < 5; k++) hreg[k] = hval[k] ? __ldg(inp + hoff[k]) : 0.f;
            const float* wp_ = w + (size_t)(ci + 1) * wstride;
            #pragma unroll
            for (int k = 0; k < 4; k++) wreg[k] = wvalid[k] ? __ldg(wp_ + wbase[k]) : 0.f;
        }

        const float2* wp = &w_s2[cg * 4 * 27];
        #pragma unroll
        for (int dz = 0; dz < 3; dz++) {
            #pragma unroll
            for (int dy = 0; dy < 3; dy++) {
                const float* row = &in_s[(dz * 10 + ty + dy) * 36 + tx * 8];
                float4 a4 = *(const float4*)row;
                float4 b4 = *(const float4*)(row + 4);
                float2 c2 = *(const float2*)(row + 8);
                float v[10] = {a4.x, a4.y, a4.z, a4.w, b4.x, b4.y, b4.z, b4.w, c2.x, c2.y};
                u64 p[9];
                #pragma unroll
                for (int i = 0; i < 9; i++) p[i] = pk2(v[i], v[i + 1]);
                const int tb = dz * 9 + dy * 3;
                #pragma unroll
                for (int co = 0; co < 4; co++) {
                    const float2* wc = wp + co * 27 + tb;
                    u64 w0 = *(const u64*)(wc + 0);
                    fma2(acc[co][0], p[0], w0); fma2(acc[co][1], p[2], w0);
                    fma2(acc[co][2], p[4], w0); fma2(acc[co][3], p[6], w0);
                    u64 w1 = *(const u64*)(wc + 1);
                    fma2(acc[co][0], p[1], w1); fma2(acc[co][1], p[3], w1);
                    fma2(acc[co][2], p[5], w1); fma2(acc[co][3], p[7], w1);
                    u64 w2 = *(const u64*)(wc + 2);
                    fma2(acc[co][0], p[2], w2); fma2(acc[co][1], p[4], w2);
                    fma2(acc[co][2], p[6], w2); fma2(acc[co][3], p[8], w2);
                }
            }
        }
        __syncthreads();
    }

    const int xo = x0 + tx * 8;
    const size_t base = (size_t)zb * HW + (y0 + ty) * W_ + xo;
    #pragma unroll
    for (int co = 0; co < 4; co++) {
        int coG = coBase + cg * 4 + co;
        if (coG < Cout) {
            float2 q0 = unpk2(acc[co][0]);
            float2 q1 = unpk2(acc[co][1]);
            float2 q2 = unpk2(acc[co][2]);
            float2 q3 = unpk2(acc[co][3]);
            float* op = out + (size_t)coG * VOX + base;
            *(float4*)(op + 0) = make_float4(q0.x, q0.y, q1.x, q1.y);
            *(float4*)(op + 4) = make_float4(q2.x, q2.y, q3.x, q3.y);
        }
    }
}

// ============================ SRU kernels ============================
__global__ void si_sru_k(const float* __restrict__ g, float* __restrict__ out,
                         const float* __restrict__ add, int C, int rev)
{
    int tid = blockIdx.x * blockDim.x + threadIdx.x;
    int total = C * HW;
    if (tid >= total) return;
    int c  = tid / HW;
    int yx = tid - c * HW;

    const float* Wp = g + (size_t)(0 * C + c) * VOX + yx;
    const float* Fp = g + (size_t)(1 * C + c) * VOX + yx;
    const float* Rp = g + (size_t)(2 * C + c) * VOX + yx;
    const float* Xp = g + (size_t)(3 * C + c) * VOX + yx;
    float*       op = out + (size_t)c * VOX + yx;
    const float* ap = add ? add + (size_t)c * VOX + yx : nullptr;

    int off = rev ? (D_ - 1) * HW : 0;
    int zs  = rev ? -HW : HW;

    float f = sigm(Fp[off]);
    float Cc = 1.f - f;
    float r = sigm(Rp[off]);
    float h = r * Cc + (1.f - r) * tanhf(Xp[off]);
    op[off] = h + (ap ? ap[off] : 0.f);

    for (int t = 1; t < D_; t++) {
        off += zs;
        f  = sigm(Fp[off]);
        Cc = f * Cc + (1.f - f) * tanhf(Wp[off]);
        r  = sigm(Rp[off]);
        h  = r * Cc + (1.f - r) * tanhf(Xp[off]);
        op[off] = h + (ap ? ap[off] : 0.f);
    }
}

__global__ void do_sru_k(const float* __restrict__ g, float* __restrict__ out,
                         const float* __restrict__ add, int C)
{
    int tid = blockIdx.x * blockDim.x + threadIdx.x;
    int total = C * HW;
    if (tid >= total) return;
    int c  = tid / HW;
    int yx = tid - c * HW;

    const float* Wp = g + (size_t)(0 * C + c) * VOX + yx;
    const float* F1 = g + (size_t)(1 * C + c) * VOX + yx;
    const float* F2 = g + (size_t)(2 * C + c) * VOX + yx;
    const float* R1 = g + (size_t)(3 * C + c) * VOX + yx;
    const float* R2 = g + (size_t)(4 * C + c) * VOX + yx;
    const float* Xp = g + (size_t)(5 * C + c) * VOX + yx;
    float*       op = out + (size_t)c * VOX + yx;
    const float* ap = add ? add + (size_t)c * VOX + yx : nullptr;

    {
        float f = sigm(F1[0]);
        float Cc = 1.f - f;
        float r = sigm(R1[0]);
        op[0] = r * Cc + (1.f - r) * tanhf(Xp[0]);
        int off = 0;
        for (int t = 1; t < D_; t++) {
            off += HW;
            f  = sigm(F1[off]);
            Cc = f * Cc + (1.f - f) * tanhf(Wp[off]);
            r  = sigm(R1[off]);
            op[off] = r * Cc + (1.f - r) * tanhf(Xp[off]);
        }
    }
    {
        int off = (D_ - 1) * HW;
        float f = sigm(F2[off]);
        float Cc = 1.f - f;
        float r = sigm(R2[off]);
        float h = r * Cc + (1.f - r) * tanhf(Xp[off]);
        op[off] = op[off] + h + (ap ? ap[off] : 0.f);
        for (int t = 1; t < D_; t++) {
            off -= HW;
            f  = sigm(F2[off]);
            Cc = f * Cc + (1.f - f) * tanhf(Wp[off]);
            r  = sigm(R2[off]);
            h  = r * Cc + (1.f - r) * tanhf(Xp[off]);
            op[off] = op[off] + h + (ap ? ap[off] : 0.f);
        }
    }
}

// ============================ host ============================
static __nv_bfloat16 *s_Ahi, *s_Alo;

static inline void conv_tc(const float* in, const float* w, float* out,
                           int Cin, int Cout, int deconv)
{
    int Kpad = Cin * 32;
    int total = Cout * Kpad;
    prep_k<<<(total + 255) / 256, 256>>>(w, s_Ahi, s_Alo, Cin, Cout, Kpad, deconv, total);
    dim3 grid(D_ * 96, Cout / 64);
    conv_mma_k<<<grid, 256>>>(in, s_Ahi, s_Alo, out, Cin, Kpad, Cin * 2);
}

static inline void conv_scalar(const float* in, const float* w, float* out,
                               int Cin, int Cout, int deconv)
{
    dim3 grid(W_ / 32, (H_ / 8) * D_, (Cout + 31) / 32);
    conv3d_k<<<grid, 256>>>(in, w, out, Cin, Cout, deconv);
}

static inline void si_launch(const float* gbuf, float* out, const float* add, int C, int rev)
{
    int n = C * HW;
    si_sru_k<<<(n + 255) / 256, 256>>>(gbuf, out, add, C, rev);
}
static inline void do_launch(const float* gbuf, float* out, const float* add, int C)
{
    int n = C * HW;
    do_sru_k<<<(n + 255) / 256, 256>>>(gbuf, out, add, C);
}

extern "C" void kernel_launch(void* const* d_in, const int* in_sizes, int n_in,
                              void* d_out, int out_size)
{
    (void)in_sizes; (void)n_in; (void)out_size;
    const float* x      = (const float*)d_in[0];
    const float* w_head = (const float*)d_in[1];
    const float* w_e0   = (const float*)d_in[2];
    const float* w_e1   = (const float*)d_in[3];
    const float* w_d0   = (const float*)d_in[4];
    const float* w_d1   = (const float*)d_in[5];
    const float* w_tail = (const float*)d_in[6];
    float* out = (float*)d_out;

    float *gc, *gh, *ge0, *ge1, *gd0, *gd1;
    cudaGetSymbolAddress((void**)&gc,  g_conv);
    cudaGetSymbolAddress((void**)&gh,  g_h);
    cudaGetSymbolAddress((void**)&ge0, g_e0);
    cudaGetSymbolAddress((void**)&ge1, g_e1);
    cudaGetSymbolAddress((void**)&gd0, g_d0);
    cudaGetSymbolAddress((void**)&gd1, g_d1);
    cudaGetSymbolAddress((void**)&s_Ahi, g_Ahi);
    cudaGetSymbolAddress((void**)&s_Alo, g_Alo);

    // h = do_sru(x, w_head)          (scalar: Cin=1)
    conv_scalar(x, w_head, gc, 1, 96, 0);
    do_launch(gc, gh, nullptr, 16);
    // e0 = si_sru(h, w_e0, fwd)      (mma: 16 -> 128)
    conv_tc(gh, w_e0, gc, 16, 128, 0);
    si_launch(gc, ge0, nullptr, 32, 0);
    // e1 = si_sru(e0, w_e1, rev)     (mma: 32 -> 256)
    conv_tc(ge0, w_e1, gc, 32, 256, 0);
    si_launch(gc, ge1, nullptr, 64, 1);
    // d0 = si_sru(e1, w_d0, fwd, deconv) + e0   (mma: 64 -> 128)
    conv_tc(ge1, w_d0, gc, 64, 128, 1);
    si_launch(gc, gd0, ge0, 32, 0);
    // d1 = si_sru(d0, w_d1, rev, deconv) + h    (mma: 32 -> 64)
    conv_tc(gd0, w_d1, gc, 32, 64, 1);
    si_launch(gc, gd1, gh, 16, 1);
    // out = do_sru(d1, w_tail, deconv) + x      (scalar: Cout=6)
    conv_scalar(gd1, w_tail, gc, 16, 6, 1);
    do_launch(gc, out, x, 1);
}

// round 8
// speedup vs baseline: 2.8572x; 1.2397x over previous
#include <cuda_runtime.h>
#include <cuda_bf16.h>
#include <math.h>
#include <stdint.h>

#define D_ 31
#define H_ 96
#define W_ 96
#define HW (H_*W_)        // 9216
#define VOX (D_*HW)       // 285696

// ---- scratch (device globals; no allocation allowed) ----
__device__ float g_conv[256 * VOX];
__device__ float g_h  [16 * VOX];
__device__ float g_e0 [32 * VOX];
__device__ float g_e1 [64 * VOX];
__device__ float g_d0 [32 * VOX];
__device__ float g_d1 [16 * VOX];
__device__ __nv_bfloat16 g_Ahi[262144];   // weights bf16-hi, [M x Kpad]
__device__ __nv_bfloat16 g_Alo[262144];   // weights bf16-lo

__device__ __forceinline__ float sigm(float a) { return 1.0f / (1.0f + expf(-a)); }

typedef unsigned long long u64;
__device__ __forceinline__ void fma2(u64& d, u64 a, u64 b) {
    asm("fma.rn.f32x2 %0, %1, %2, %0;" : "+l"(d) : "l"(a), "l"(b));
}
__device__ __forceinline__ u64 pk2(float x, float y) {
    u64 r; asm("mov.b64 %0, {%1, %2};" : "=l"(r) : "f"(x), "f"(y)); return r;
}
__device__ __forceinline__ float2 unpk2(u64 a) {
    float x, y; asm("mov.b64 {%0, %1}, %2;" : "=f"(x), "=f"(y) : "l"(a));
    return make_float2(x, y);
}
__device__ __forceinline__ uint32_t smem_u32(const void* p) {
    uint32_t a;
    asm("{ .reg .u64 t; cvta.to.shared.u64 t, %1; cvt.u32.u64 %0, t; }" : "=r"(a) : "l"(p));
    return a;
}
__device__ __forceinline__ void ldsm4(uint32_t* r, uint32_t addr) {
    asm volatile("ldmatrix.sync.aligned.m8n8.x4.shared.b16 {%0,%1,%2,%3}, [%4];"
                 : "=r"(r[0]), "=r"(r[1]), "=r"(r[2]), "=r"(r[3]) : "r"(addr));
}
__device__ __forceinline__ void mma16816(float* c, const uint32_t* a, uint32_t b0, uint32_t b1) {
    asm volatile("mma.sync.aligned.m16n8k16.row.col.f32.bf16.bf16.f32 "
                 "{%0,%1,%2,%3},{%4,%5,%6,%7},{%8,%9},{%0,%1,%2,%3};"
                 : "+f"(c[0]), "+f"(c[1]), "+f"(c[2]), "+f"(c[3])
                 : "r"(a[0]), "r"(a[1]), "r"(a[2]), "r"(a[3]), "r"(b0), "r"(b1));
}
// pack truncated-hi bf16 of two floats: low half <- a, high half <- b
__device__ __forceinline__ uint32_t prmt_hi(float a, float b) {
    uint32_t r;
    asm("prmt.b32 %0, %1, %2, 0x7632;" : "=r"(r) : "r"(__float_as_uint(a)), "r"(__float_as_uint(b)));
    return r;
}
// pack rn bf16 of two floats: low half <- lo, high half <- hi
__device__ __forceinline__ uint32_t cvt_bf2(float hi, float lo) {
    uint32_t r;
    asm("cvt.rn.bf16x2.f32 %0, %1, %2;" : "=r"(r) : "f"(hi), "f"(lo));
    return r;
}
__device__ __forceinline__ float trunc16(float v) {
    return __uint_as_float(__float_as_uint(v) & 0xFFFF0000u);
}

// ============================================================================
// Weight prep: split fp32 weights into bf16 hi/lo, layout A[m][k], k=ci*32+t.
// ============================================================================
__global__ void prep_k(const float* __restrict__ w, __nv_bfloat16* __restrict__ Ahi,
                       __nv_bfloat16* __restrict__ Alo,
                       int Cin, int Cout, int Kpad, int deconv, int total)
{
    int i = blockIdx.x * 256 + threadIdx.x;
    if (i >= total) return;
    int m = i / Kpad, k = i - m * Kpad;
    int t = k & 31, ci = k >> 5;
    float v = 0.f;
    if (t < 27 && m < Cout && ci < Cin)
        v = deconv ? w[((size_t)ci * Cout + m) * 27 + (26 - t)]
                   : w[((size_t)m * Cin + ci) * 27 + t];
    __nv_bfloat16 h = __float2bfloat16(v);
    Ahi[i] = h;
    Alo[i] = __float2bfloat16(v - __bfloat162float(h));
}

// ============================================================================
// Tensor-core implicit-GEMM conv. Block tile: M=64 co, N=192 (96x * 2y).
// 8 warps = 2M x 4N (warp 32x48). K chunks of 16 (half a ci).
// Raw input tile (12 rows x 100) in smem per ci (coalesced, zero-padded);
// B fragments built in registers straight from raw tile (no B smem staging).
// A via smem stage + ldmatrix (KS=24 padded, conflict-free).
// ============================================================================
#define KS 24
#define AS_E (64*KS)
#define RAW_E 1200        // 12 rows * 100

__global__ __launch_bounds__(256)
void conv_mma_k(const float* __restrict__ in,
                const __nv_bfloat16* __restrict__ Ahi,
                const __nv_bfloat16* __restrict__ Alo,
                float* __restrict__ out,
                int Cin, int Kpad, int NC2)
{
    __shared__ __align__(16) __nv_bfloat16 AsH[2][AS_E], AsL[2][AS_E];
    __shared__ __align__(16) float rawS[2][RAW_E];

    const int tid  = threadIdx.x;
    const int wid  = tid >> 5, lane = tid & 31;
    const int g    = lane >> 2, t4 = lane & 3;
    const int bx   = blockIdx.x, mb = blockIdx.y;
    const int z    = bx / 48, y0 = (bx - z * 48) * 2;

    const int m0  = (wid >> 2) * 32;
    const int nw  = wid & 3;
    const int n0w = nw * 48;
    const int yp  = nw >> 1;            // warp-uniform y row (0/1)
    const int xw  = n0w - 96 * yp;      // x base of this warp (0 or 48)

    // ---- raw tile slot descriptors (loop-invariant) ----
    int  roff[5]; bool rvalid[5];
    #pragma unroll
    for (int k = 0; k < 5; k++) {
        int i = tid + k * 256;
        if (i < RAW_E) {
            int row = i / 100, col = i - row * 100;
            int zz = z + (row >> 2) - 1;
            int gy = y0 + (row & 3) - 1;
            int gx = col - 1;
            rvalid[k] = (col < 98) && ((unsigned)zz < D_) && ((unsigned)gy < H_) && ((unsigned)gx < W_);
            roff[k] = zz * HW + gy * 96 + gx;
        } else { rvalid[k] = false; roff[k] = 0; }
    }

    // ---- A staging descriptors ----
    const int kp = tid & 7, rb = tid >> 3;        // rb 0..31
    const uint32_t offA = (uint32_t)(((lane & 7) + ((lane >> 3) & 1) * 8) * KS + (lane >> 4) * 8) * 2;
    const uint32_t baAH = smem_u32(AsH), baAL = smem_u32(AsL);

    float acc[2][6][4];
    #pragma unroll
    for (int mt = 0; mt < 2; mt++)
        #pragma unroll
        for (int nt = 0; nt < 6; nt++)
            #pragma unroll
            for (int j = 0; j < 4; j++) acc[mt][nt][j] = 0.f;

    uint32_t avh[2], avl[2];
    float rreg[5];

    auto loadA = [&](int c) {
        const size_t ab = (size_t)(mb * 64 + rb) * Kpad + c * 16 + 2 * kp;
        avh[0] = *(const uint32_t*)(Ahi + ab);
        avh[1] = *(const uint32_t*)(Ahi + ab + (size_t)32 * Kpad);
        avl[0] = *(const uint32_t*)(Alo + ab);
        avl[1] = *(const uint32_t*)(Alo + ab + (size_t)32 * Kpad);
    };
    auto stsA = [&](int st) {
        #pragma unroll
        for (int r = 0; r < 2; r++) {
            int m = rb + r * 32;
            *(uint32_t*)&AsH[st][m * KS + 2 * kp] = avh[r];
            *(uint32_t*)&AsL[st][m * KS + 2 * kp] = avl[r];
        }
    };

    // ---- prologue: raw(ci=0) + A(chunk 0) ----
    #pragma unroll
    for (int k = 0; k < 5; k++) rreg[k] = rvalid[k] ? __ldg(in + roff[k]) : 0.f;
    #pragma unroll
    for (int k = 0; k < 5; k++) {
        int i = tid + k * 256;
        if (i < RAW_E) rawS[0][i] = rreg[k];
    }
    loadA(0);
    stsA(0);
    __syncthreads();

    for (int c = 0; c < NC2; c++) {
        const int ci = c >> 1, st = c & 1;
        const bool more = (c + 1 < NC2);
        const bool evenPf = (!(c & 1)) && (ci + 1 < Cin);
        const bool oddSt  = ((c & 1))  && (ci + 1 < Cin);

        if (more) loadA(c + 1);
        if (evenPf) {
            const float* inp = in + (size_t)(ci + 1) * VOX;
            #pragma unroll
            for (int k = 0; k < 5; k++) rreg[k] = rvalid[k] ? __ldg(inp + roff[k]) : 0.f;
        }

        // A fragments
        uint32_t ah0[4], ah1[4], al0[4], al1[4];
        const uint32_t sa = st * (AS_E * 2);
        ldsm4(ah0, baAH + sa + m0 * (KS*2) + offA);
        ldsm4(ah1, baAH + sa + (m0 + 16) * (KS*2) + offA);
        ldsm4(al0, baAL + sa + m0 * (KS*2) + offA);
        ldsm4(al1, baAL + sa + (m0 + 16) * (KS*2) + offA);

        // B tap bases for this chunk (4 k-values per lane: t0+2t4 +{0,1,8,9})
        const int t0 = st * 16;
        const float* rp = rawS[ci & 1];
        int tbase[4]; bool tval[4];
        #pragma unroll
        for (int q = 0; q < 4; q++) {
            int t = t0 + 2 * t4 + (q & 1) + (q >> 1) * 8;
            tval[q] = (t < 27);
            int tt = tval[q] ? t : 0;
            int dz = tt / 9, r9 = tt - dz * 9;
            int dy = r9 / 3, dx = r9 - dy * 3;
            tbase[q] = (dz * 4 + dy + yp) * 100 + xw + g + dx;
        }

        #pragma unroll
        for (int nt = 0; nt < 6; nt++) {
            const int o = nt * 8;
            float vA = tval[0] ? rp[tbase[0] + o] : 0.f;
            float vB = tval[1] ? rp[tbase[1] + o] : 0.f;
            float vC = tval[2] ? rp[tbase[2] + o] : 0.f;
            float vD = tval[3] ? rp[tbase[3] + o] : 0.f;
            uint32_t b0h = prmt_hi(vA, vB);
            uint32_t b1h = prmt_hi(vC, vD);
            uint32_t b0l = cvt_bf2(vB - trunc16(vB), vA - trunc16(vA));
            uint32_t b1l = cvt_bf2(vD - trunc16(vD), vC - trunc16(vC));
            mma16816(acc[0][nt], ah0, b0h, b1h);
            mma16816(acc[0][nt], al0, b0h, b1h);
            mma16816(acc[0][nt], ah0, b0l, b1l);
            mma16816(acc[1][nt], ah1, b0h, b1h);
            mma16816(acc[1][nt], al1, b0h, b1h);
            mma16816(acc[1][nt], ah1, b0l, b1l);
        }

        if (oddSt) {
            float* rw = rawS[(ci + 1) & 1];
            #pragma unroll
            for (int k = 0; k < 5; k++) {
                int i = tid + k * 256;
                if (i < RAW_E) rw[i] = rreg[k];
            }
        }
        if (more) stsA(1 - st);
        __syncthreads();
    }

    // epilogue: Cout multiple of 64 for all mma layers
    const size_t zy = (size_t)z * HW + (size_t)(y0 + yp) * 96;
    #pragma unroll
    for (int mt = 0; mt < 2; mt++) {
        int co = mb * 64 + m0 + mt * 16 + g;
        #pragma unroll
        for (int nt = 0; nt < 6; nt++) {
            int x = xw + nt * 8 + t4 * 2;
            float* op = out + (size_t)co * VOX + zy + x;
            *(float2*)op = make_float2(acc[mt][nt][0], acc[mt][nt][1]);
            *(float2*)(op + (size_t)8 * VOX) = make_float2(acc[mt][nt][2], acc[mt][nt][3]);
        }
    }
}

// ============================================================================
// Scalar FFMA2 conv (head Cin=1 and tail Cout=6 layers).
// ============================================================================
#define HALO 1080
#define WTOT 864

__global__ __launch_bounds__(256, 2)
void conv3d_k(const float* __restrict__ in, const float* __restrict__ w,
              float* __restrict__ out, int Cin, int Cout, int deconv)
{
    __shared__ __align__(16) float  in_s[HALO];
    __shared__ __align__(8)  float2 w_s2[WTOT];

    const int tid = threadIdx.x;
    const int tx  = tid & 3;
    const int ty  = (tid >> 2) & 7;
    const int cg  = tid >> 5;

    const int x0 = blockIdx.x * 32;
    const int y0 = (blockIdx.y % 12) * 8;
    const int zb = blockIdx.y / 12;
    const int coBase = blockIdx.z * 32;

    int  hoff[5]; bool hval[5];
    #pragma unroll
    for (int k = 0; k < 5; k++) {
        int i = tid + k * 256;
        if (i < HALO) {
            int dz  = i / 360;
            int rem = i - dz * 360;
            int yy  = rem / 36;
            int xx  = rem - yy * 36;
            int z = zb + dz - 1, y = y0 + yy - 1, x = x0 + xx - 1;
            hval[k] = ((unsigned)z < D_) && ((unsigned)y < H_) && ((unsigned)x < W_) && (xx < 34);
            hoff[k] = z * HW + y * W_ + x;
        } else { hval[k] = false; hoff[k] = 0; }
    }
    int wbase[4]; bool wvalid[4];
    const int wstride = deconv ? Cout * 27 : 27;
    #pragma unroll
    for (int k = 0; k < 4; k++) {
        int idx = tid + k * 256;
        if (idx < WTOT) {
            int co = idx / 27, t = idx - co * 27;
            int coG = coBase + co;
            wvalid[k] = (coG < Cout);
            wbase[k]  = deconv ? (coG * 27 + (26 - t)) : (coG * Cin * 27 + t);
        } else { wvalid[k] = false; wbase[k] = 0; }
    }

    u64 acc[4][4];
    #pragma unroll
    for (int c = 0; c < 4; c++)
        #pragma unroll
        for (int j = 0; j < 4; j++) acc[c][j] = 0ull;

    float hreg[5], wreg[4];
    #pragma unroll
    for (int k = 0; k < 5; k++) hreg[k] = hval[k] ? __ldg(in + hoff[k]) : 0.f;
    #pragma unroll
    for (int k = 0; k < 4; k++) wreg[k] = wvalid[k] ? __ldg(w + wbase[k]) : 0.f;

    for (int ci = 0; ci < Cin; ci++) {
        #pragma unroll
        for (int k = 0; k < 5; k++) {
            int i = tid + k * 256;
            if (i < HALO) in_s[i] = hreg[k];
        }
        #pragma unroll
        for (int k = 0; k < 4; k++) {
            int idx = tid + k * 256;
            if (idx < WTOT) w_s2[idx] = make_float2(wreg[k], wreg[k]);
        }
        __syncthreads();

        if (ci + 1 < Cin) {
            const float* inp = in + (size_t)(ci + 1) * VOX;
            #pragma unroll
            for (int k = 0; k < 5; k++) hreg[k] = hval[k] ? __ldg(inp + hoff[k]) : 0.f;
            const float* wp_ = w + (size_t)(ci + 1) * wstride;
            #pragma unroll
            for (int k = 0; k < 4; k++) wreg[k] = wvalid[k] ? __ldg(wp_ + wbase[k]) : 0.f;
        }

        const float2* wp = &w_s2[cg * 4 * 27];
        #pragma unroll
        for (int dz = 0; dz < 3; dz++) {
            #pragma unroll
            for (int dy = 0; dy < 3; dy++) {
                const float* row = &in_s[(dz * 10 + ty + dy) * 36 + tx * 8];
                float4 a4 = *(const float4*)row;
                float4 b4 = *(const float4*)(row + 4);
                float2 c2 = *(const float2*)(row + 8);
                float v[10] = {a4.x, a4.y, a4.z, a4.w, b4.x, b4.y, b4.z, b4.w, c2.x, c2.y};
                u64 p[9];
                #pragma unroll
                for (int i = 0; i < 9; i++) p[i] = pk2(v[i], v[i + 1]);
                const int tb = dz * 9 + dy * 3;
                #pragma unroll
                for (int co = 0; co < 4; co++) {
                    const float2* wc = wp + co * 27 + tb;
                    u64 w0 = *(const u64*)(wc + 0);
                    fma2(acc[co][0], p[0], w0); fma2(acc[co][1], p[2], w0);
                    fma2(acc[co][2], p[4], w0); fma2(acc[co][3], p[6], w0);
                    u64 w1 = *(const u64*)(wc + 1);
                    fma2(acc[co][0], p[1], w1); fma2(acc[co][1], p[3], w1);
                    fma2(acc[co][2], p[5], w1); fma2(acc[co][3], p[7], w1);
                    u64 w2 = *(const u64*)(wc + 2);
                    fma2(acc[co][0], p[2], w2); fma2(acc[co][1], p[4], w2);
                    fma2(acc[co][2], p[6], w2); fma2(acc[co][3], p[8], w2);
                }
            }
        }
        __syncthreads();
    }

    const int xo = x0 + tx * 8;
    const size_t base = (size_t)zb * HW + (y0 + ty) * W_ + xo;
    #pragma unroll
    for (int co = 0; co < 4; co++) {
        int coG = coBase + cg * 4 + co;
        if (coG < Cout) {
            float2 q0 = unpk2(acc[co][0]);
            float2 q1 = unpk2(acc[co][1]);
            float2 q2 = unpk2(acc[co][2]);
            float2 q3 = unpk2(acc[co][3]);
            float* op = out + (size_t)coG * VOX + base;
            *(float4*)(op + 0) = make_float4(q0.x, q0.y, q1.x, q1.y);
            *(float4*)(op + 4) = make_float4(q2.x, q2.y, q3.x, q3.y);
        }
    }
}

// ============================ SRU kernels ============================
__global__ void si_sru_k(const float* __restrict__ g, float* __restrict__ out,
                         const float* __restrict__ add, int C, int rev)
{
    int tid = blockIdx.x * blockDim.x + threadIdx.x;
    int total = C * HW;
    if (tid >= total) return;
    int c  = tid / HW;
    int yx = tid - c * HW;

    const float* Wp = g + (size_t)(0 * C + c) * VOX + yx;
    const float* Fp = g + (size_t)(1 * C + c) * VOX + yx;
    const float* Rp = g + (size_t)(2 * C + c) * VOX + yx;
    const float* Xp = g + (size_t)(3 * C + c) * VOX + yx;
    float*       op = out + (size_t)c * VOX + yx;
    const float* ap = add ? add + (size_t)c * VOX + yx : nullptr;

    int off = rev ? (D_ - 1) * HW : 0;
    int zs  = rev ? -HW : HW;

    float f = sigm(Fp[off]);
    float Cc = 1.f - f;
    float r = sigm(Rp[off]);
    float h = r * Cc + (1.f - r) * tanhf(Xp[off]);
    op[off] = h + (ap ? ap[off] : 0.f);

    for (int t = 1; t < D_; t++) {
        off += zs;
        f  = sigm(Fp[off]);
        Cc = f * Cc + (1.f - f) * tanhf(Wp[off]);
        r  = sigm(Rp[off]);
        h  = r * Cc + (1.f - r) * tanhf(Xp[off]);
        op[off] = h + (ap ? ap[off] : 0.f);
    }
}

__global__ void do_sru_k(const float* __restrict__ g, float* __restrict__ out,
                         const float* __restrict__ add, int C)
{
    int tid = blockIdx.x * blockDim.x + threadIdx.x;
    int total = C * HW;
    if (tid >= total) return;
    int c  = tid / HW;
    int yx = tid - c * HW;

    const float* Wp = g + (size_t)(0 * C + c) * VOX + yx;
    const float* F1 = g + (size_t)(1 * C + c) * VOX + yx;
    const float* F2 = g + (size_t)(2 * C + c) * VOX + yx;
    const float* R1 = g + (size_t)(3 * C + c) * VOX + yx;
    const float* R2 = g + (size_t)(4 * C + c) * VOX + yx;
    const float* Xp = g + (size_t)(5 * C + c) * VOX + yx;
    float*       op = out + (size_t)c * VOX + yx;
    const float* ap = add ? add + (size_t)c * VOX + yx : nullptr;

    {
        float f = sigm(F1[0]);
        float Cc = 1.f - f;
        float r = sigm(R1[0]);
        op[0] = r * Cc + (1.f - r) * tanhf(Xp[0]);
        int off = 0;
        for (int t = 1; t < D_; t++) {
            off += HW;
            f  = sigm(F1[off]);
            Cc = f * Cc + (1.f - f) * tanhf(Wp[off]);
            r  = sigm(R1[off]);
            op[off] = r * Cc + (1.f - r) * tanhf(Xp[off]);
        }
    }
    {
        int off = (D_ - 1) * HW;
        float f = sigm(F2[off]);
        float Cc = 1.f - f;
        float r = sigm(R2[off]);
        float h = r * Cc + (1.f - r) * tanhf(Xp[off]);
        op[off] = op[off] + h + (ap ? ap[off] : 0.f);
        for (int t = 1; t < D_; t++) {
            off -= HW;
            f  = sigm(F2[off]);
            Cc = f * Cc + (1.f - f) * tanhf(Wp[off]);
            r  = sigm(R2[off]);
            h  = r * Cc + (1.f - r) * tanhf(Xp[off]);
            op[off] = op[off] + h + (ap ? ap[off] : 0.f);
        }
    }
}

// ============================ host ============================
static __nv_bfloat16 *s_Ahi, *s_Alo;

static inline void conv_tc(const float* in, const float* w, float* out,
                           int Cin, int Cout, int deconv)
{
    int Kpad = Cin * 32;
    int total = Cout * Kpad;
    prep_k<<<(total + 255) / 256, 256>>>(w, s_Ahi, s_Alo, Cin, Cout, Kpad, deconv, total);
    dim3 grid(D_ * 48, Cout / 64);
    conv_mma_k<<<grid, 256>>>(in, s_Ahi, s_Alo, out, Cin, Kpad, Cin * 2);
}

static inline void conv_scalar(const float* in, const float* w, float* out,
                               int Cin, int Cout, int deconv)
{
    dim3 grid(W_ / 32, (H_ / 8) * D_, (Cout + 31) / 32);
    conv3d_k<<<grid, 256>>>(in, w, out, Cin, Cout, deconv);
}

static inline void si_launch(const float* gbuf, float* out, const float* add, int C, int rev)
{
    int n = C * HW;
    si_sru_k<<<(n + 255) / 256, 256>>>(gbuf, out, add, C, rev);
}
static inline void do_launch(const float* gbuf, float* out, const float* add, int C)
{
    int n = C * HW;
    do_sru_k<<<(n + 255) / 256, 256>>>(gbuf, out, add, C);
}

extern "C" void kernel_launch(void* const* d_in, const int* in_sizes, int n_in,
                              void* d_out, int out_size)
{
    (void)in_sizes; (void)n_in; (void)out_size;
    const float* x      = (const float*)d_in[0];
    const float* w_head = (const float*)d_in[1];
    const float* w_e0   = (const float*)d_in[2];
    const float* w_e1   = (const float*)d_in[3];
    const float* w_d0   = (const float*)d_in[4];
    const float* w_d1   = (const float*)d_in[5];
    const float* w_tail = (const float*)d_in[6];
    float* out = (float*)d_out;

    float *gc, *gh, *ge0, *ge1, *gd0, *gd1;
    cudaGetSymbolAddress((void**)&gc,  g_conv);
    cudaGetSymbolAddress((void**)&gh,  g_h);
    cudaGetSymbolAddress((void**)&ge0, g_e0);
    cudaGetSymbolAddress((void**)&ge1, g_e1);
    cudaGetSymbolAddress((void**)&gd0, g_d0);
    cudaGetSymbolAddress((void**)&gd1, g_d1);
    cudaGetSymbolAddress((void**)&s_Ahi, g_Ahi);
    cudaGetSymbolAddress((void**)&s_Alo, g_Alo);

    // h = do_sru(x, w_head)          (scalar: Cin=1)
    conv_scalar(x, w_head, gc, 1, 96, 0);
    do_launch(gc, gh, nullptr, 16);
    // e0 = si_sru(h, w_e0, fwd)      (mma: 16 -> 128)
    conv_tc(gh, w_e0, gc, 16, 128, 0);
    si_launch(gc, ge0, nullptr, 32, 0);
    // e1 = si_sru(e0, w_e1, rev)     (mma: 32 -> 256)
    conv_tc(ge0, w_e1, gc, 32, 256, 0);
    si_launch(gc, ge1, nullptr, 64, 1);
    // d0 = si_sru(e1, w_d0, fwd, deconv) + e0   (mma: 64 -> 128)
    conv_tc(ge1, w_d0, gc, 64, 128, 1);
    si_launch(gc, gd0, ge0, 32, 0);
    // d1 = si_sru(d0, w_d1, rev, deconv) + h    (mma: 32 -> 64)
    conv_tc(gd0, w_d1, gc, 32, 64, 1);
    si_launch(gc, gd1, gh, 16, 1);
    // out = do_sru(d1, w_tail, deconv) + x      (scalar: Cout=6)
    conv_scalar(gd1, w_tail, gc, 16, 6, 1);
    do_launch(gc, out, x, 1);
}

// round 9
// speedup vs baseline: 3.2852x; 1.1498x over previous
#include <cuda_runtime.h>
#include <cuda_bf16.h>
#include <math.h>
#include <stdint.h>

#define D_ 31
#define H_ 96
#define W_ 96
#define HW (H_*W_)        // 9216
#define VOX (D_*HW)       // 285696

// ---- scratch (device globals; no allocation allowed) ----
__device__ float g_conv[256 * VOX];
__device__ float g_h  [16 * VOX];
__device__ float g_e0 [32 * VOX];
__device__ float g_e1 [64 * VOX];
__device__ float g_d0 [32 * VOX];
__device__ float g_d1 [16 * VOX];
__device__ __nv_bfloat16 g_Ahi[262144];   // weights bf16-hi, [M x Kpad]
__device__ __nv_bfloat16 g_Alo[262144];   // weights bf16-lo

__device__ __forceinline__ float sigm(float a) { return 1.0f / (1.0f + expf(-a)); }

typedef unsigned long long u64;
__device__ __forceinline__ void fma2(u64& d, u64 a, u64 b) {
    asm("fma.rn.f32x2 %0, %1, %2, %0;" : "+l"(d) : "l"(a), "l"(b));
}
__device__ __forceinline__ u64 pk2(float x, float y) {
    u64 r; asm("mov.b64 %0, {%1, %2};" : "=l"(r) : "f"(x), "f"(y)); return r;
}
__device__ __forceinline__ float2 unpk2(u64 a) {
    float x, y; asm("mov.b64 {%0, %1}, %2;" : "=f"(x), "=f"(y) : "l"(a));
    return make_float2(x, y);
}
__device__ __forceinline__ uint32_t smem_u32(const void* p) {
    uint32_t a;
    asm("{ .reg .u64 t; cvta.to.shared.u64 t, %1; cvt.u32.u64 %0, t; }" : "=r"(a) : "l"(p));
    return a;
}
__device__ __forceinline__ void ldsm4(uint32_t* r, uint32_t addr) {
    asm volatile("ldmatrix.sync.aligned.m8n8.x4.shared.b16 {%0,%1,%2,%3}, [%4];"
                 : "=r"(r[0]), "=r"(r[1]), "=r"(r[2]), "=r"(r[3]) : "r"(addr));
}
__device__ __forceinline__ void mma16816(float* c, const uint32_t* a, uint32_t b0, uint32_t b1) {
    asm volatile("mma.sync.aligned.m16n8k16.row.col.f32.bf16.bf16.f32 "
                 "{%0,%1,%2,%3},{%4,%5,%6,%7},{%8,%9},{%0,%1,%2,%3};"
                 : "+f"(c[0]), "+f"(c[1]), "+f"(c[2]), "+f"(c[3])
                 : "r"(a[0]), "r"(a[1]), "r"(a[2]), "r"(a[3]), "r"(b0), "r"(b1));
}
// pack truncated-hi bf16 of two floats: low half <- a, high half <- b
__device__ __forceinline__ uint32_t prmt_hi(float a, float b) {
    uint32_t r;
    asm("prmt.b32 %0, %1, %2, 0x7632;" : "=r"(r) : "r"(__float_as_uint(a)), "r"(__float_as_uint(b)));
    return r;
}
// pack rn bf16 of two floats: high half <- hi, low half <- lo
__device__ __forceinline__ uint32_t cvt_bf2(float hi, float lo) {
    uint32_t r;
    asm("cvt.rn.bf16x2.f32 %0, %1, %2;" : "=r"(r) : "f"(hi), "f"(lo));
    return r;
}
__device__ __forceinline__ float trunc16(float v) {
    return __uint_as_float(__float_as_uint(v) & 0xFFFF0000u);
}

// ============================================================================
// Weight prep: split fp32 weights into bf16 hi/lo, layout A[m][k], k=ci*32+t.
// ============================================================================
__global__ void prep_k(const float* __restrict__ w, __nv_bfloat16* __restrict__ Ahi,
                       __nv_bfloat16* __restrict__ Alo,
                       int Cin, int Cout, int Kpad, int deconv, int total)
{
    int i = blockIdx.x * 256 + threadIdx.x;
    if (i >= total) return;
    int m = i / Kpad, k = i - m * Kpad;
    int t = k & 31, ci = k >> 5;
    float v = 0.f;
    if (t < 27 && m < Cout && ci < Cin)
        v = deconv ? w[((size_t)ci * Cout + m) * 27 + (26 - t)]
                   : w[((size_t)m * Cin + ci) * 27 + t];
    __nv_bfloat16 h = __float2bfloat16(v);
    Ahi[i] = h;
    Alo[i] = __float2bfloat16(v - __bfloat162float(h));
}

// ============================================================================
// Tensor-core implicit-GEMM conv. Block tile: M=64 co, N=192 (96x * 2y).
// 8 warps, each: full M=64 x 24 N (distinct N -> no duplicate B-build).
// K chunks of 16. Raw input tile (12 rows x 100 + zero pad) in smem per ci;
// B fragments built in regs from raw tile; taps precomputed per parity,
// invalid taps read the zero pad (no selects).
// ============================================================================
#define KS 24
#define AS_E (64*KS)
#define RAW_E 1200        // 12 rows * 100
#define RAW_T 1328        // + 128 zero-pad floats

__global__ __launch_bounds__(256)
void conv_mma_k(const float* __restrict__ in,
                const __nv_bfloat16* __restrict__ Ahi,
                const __nv_bfloat16* __restrict__ Alo,
                float* __restrict__ out,
                int Cin, int Kpad, int NC2)
{
    __shared__ __align__(16) __nv_bfloat16 AsH[2][AS_E], AsL[2][AS_E];
    __shared__ __align__(16) float rawS[2][RAW_T];

    const int tid  = threadIdx.x;
    const int wid  = tid >> 5, lane = tid & 31;
    const int g    = lane >> 2, t4 = lane & 3;
    const int bx   = blockIdx.x, mb = blockIdx.y;
    const int z    = bx / 48, y0 = (bx - z * 48) * 2;

    const int yp = wid >> 2;           // warp-uniform y row (0/1)
    const int xw = (wid & 3) * 24;     // warp x base

    // ---- raw tile slot descriptors (loop-invariant) ----
    int  roff[5]; bool rvalid[5];
    #pragma unroll
    for (int k = 0; k < 5; k++) {
        int i = tid + k * 256;
        if (i < RAW_E) {
            int row = i / 100, col = i - row * 100;
            int zz = z + (row >> 2) - 1;
            int gy = y0 + (row & 3) - 1;
            int gx = col - 1;
            rvalid[k] = (col < 98) && ((unsigned)zz < D_) && ((unsigned)gy < H_) && ((unsigned)gx < W_);
            roff[k] = zz * HW + gy * 96 + gx;
        } else { rvalid[k] = false; roff[k] = 0; }
    }

    // ---- per-parity tap bases (loop-invariant; invalid -> zero pad) ----
    int tb[2][4];
    #pragma unroll
    for (int par = 0; par < 2; par++) {
        #pragma unroll
        for (int q = 0; q < 4; q++) {
            int t = par * 16 + 2 * t4 + (q & 1) + (q >> 1) * 8;
            if (t < 27) {
                int dz = t / 9, r9 = t - dz * 9;
                int dy = r9 / 3, dx = r9 - dy * 3;
                tb[par][q] = (dz * 4 + dy + yp) * 100 + xw + g + dx;
            } else {
                tb[par][q] = RAW_E + g;
            }
        }
    }

    // ---- A staging descriptors ----
    const int kp = tid & 7, rb = tid >> 3;        // rb 0..31
    const uint32_t offA = (uint32_t)(((lane & 7) + ((lane >> 3) & 1) * 8) * KS + (lane >> 4) * 8) * 2;
    const uint32_t baAH = smem_u32(AsH), baAL = smem_u32(AsL);

    float acc[4][3][4];
    #pragma unroll
    for (int mt = 0; mt < 4; mt++)
        #pragma unroll
        for (int nt = 0; nt < 3; nt++)
            #pragma unroll
            for (int j = 0; j < 4; j++) acc[mt][nt][j] = 0.f;

    uint32_t avh[2], avl[2];
    float rreg[5];

    auto loadA = [&](int c) {
        const size_t ab = (size_t)(mb * 64 + rb) * Kpad + c * 16 + 2 * kp;
        avh[0] = *(const uint32_t*)(Ahi + ab);
        avh[1] = *(const uint32_t*)(Ahi + ab + (size_t)32 * Kpad);
        avl[0] = *(const uint32_t*)(Alo + ab);
        avl[1] = *(const uint32_t*)(Alo + ab + (size_t)32 * Kpad);
    };
    auto stsA = [&](int st) {
        #pragma unroll
        for (int r = 0; r < 2; r++) {
            int m = rb + r * 32;
            *(uint32_t*)&AsH[st][m * KS + 2 * kp] = avh[r];
            *(uint32_t*)&AsL[st][m * KS + 2 * kp] = avl[r];
        }
    };

    // ---- prologue: zero pads, raw(ci=0), A(chunk 0) ----
    if (tid < RAW_T - RAW_E) {
        rawS[0][RAW_E + tid] = 0.f;
        rawS[1][RAW_E + tid] = 0.f;
    }
    #pragma unroll
    for (int k = 0; k < 5; k++) rreg[k] = rvalid[k] ? __ldg(in + roff[k]) : 0.f;
    #pragma unroll
    for (int k = 0; k < 5; k++) {
        int i = tid + k * 256;
        if (i < RAW_E) rawS[0][i] = rreg[k];
    }
    loadA(0);
    stsA(0);
    __syncthreads();

    for (int c = 0; c < NC2; c++) {
        const int ci = c >> 1, st = c & 1;
        const bool more = (c + 1 < NC2);
        const bool evenPf = (!(c & 1)) && (ci + 1 < Cin);
        const bool oddSt  = ((c & 1))  && (ci + 1 < Cin);

        if (more) loadA(c + 1);
        if (evenPf) {
            const float* inp = in + (size_t)(ci + 1) * VOX;
            #pragma unroll
            for (int k = 0; k < 5; k++) rreg[k] = rvalid[k] ? __ldg(inp + roff[k]) : 0.f;
        }

        // ---- B fragments (3 n-tiles), built once per warp ----
        const float* rp = rawS[ci & 1];
        const int* tq = tb[st];
        uint32_t bh[3][2], bl[3][2];
        #pragma unroll
        for (int nt = 0; nt < 3; nt++) {
            const int o = nt * 8;
            float vA = rp[tq[0] + o];
            float vB = rp[tq[1] + o];
            float vC = rp[tq[2] + o];
            float vD = rp[tq[3] + o];
            bh[nt][0] = prmt_hi(vA, vB);
            bh[nt][1] = prmt_hi(vC, vD);
            bl[nt][0] = cvt_bf2(vB - trunc16(vB), vA - trunc16(vA));
            bl[nt][1] = cvt_bf2(vD - trunc16(vD), vC - trunc16(vC));
        }

        // ---- A fragments per 16-row tile, 3 MMAs each ----
        const uint32_t sa = st * (AS_E * 2);
        #pragma unroll
        for (int mt = 0; mt < 4; mt++) {
            uint32_t ah[4], al[4];
            ldsm4(ah, baAH + sa + (mt * 16) * (KS*2) + offA);
            ldsm4(al, baAL + sa + (mt * 16) * (KS*2) + offA);
            #pragma unroll
            for (int nt = 0; nt < 3; nt++) {
                mma16816(acc[mt][nt], ah, bh[nt][0], bh[nt][1]);
                mma16816(acc[mt][nt], al, bh[nt][0], bh[nt][1]);
                mma16816(acc[mt][nt], ah, bl[nt][0], bl[nt][1]);
            }
        }

        if (oddSt) {
            float* rw = rawS[(ci + 1) & 1];
            #pragma unroll
            for (int k = 0; k < 5; k++) {
                int i = tid + k * 256;
                if (i < RAW_E) rw[i] = rreg[k];
            }
        }
        if (more) stsA(1 - st);
        __syncthreads();
    }

    // epilogue: Cout multiple of 64 for all mma layers
    const size_t zy = (size_t)z * HW + (size_t)(y0 + yp) * 96;
    #pragma unroll
    for (int mt = 0; mt < 4; mt++) {
        int co = mb * 64 + mt * 16 + g;
        #pragma unroll
        for (int nt = 0; nt < 3; nt++) {
            int x = xw + nt * 8 + t4 * 2;
            float* op = out + (size_t)co * VOX + zy + x;
            *(float2*)op = make_float2(acc[mt][nt][0], acc[mt][nt][1]);
            *(float2*)(op + (size_t)8 * VOX) = make_float2(acc[mt][nt][2], acc[mt][nt][3]);
        }
    }
}

// ============================================================================
// Scalar FFMA2 conv (head Cin=1 and tail Cout=6 layers).
// ============================================================================
#define HALO 1080
#define WTOT 864

__global__ __launch_bounds__(256, 2)
void conv3d_k(const float* __restrict__ in, const float* __restrict__ w,
              float* __restrict__ out, int Cin, int Cout, int deconv)
{
    __shared__ __align__(16) float  in_s[HALO];
    __shared__ __align__(8)  float2 w_s2[WTOT];

    const int tid = threadIdx.x;
    const int tx  = tid & 3;
    const int ty  = (tid >> 2) & 7;
    const int cg  = tid >> 5;

    const int x0 = blockIdx.x * 32;
    const int y0 = (blockIdx.y % 12) * 8;
    const int zb = blockIdx.y / 12;
    const int coBase = blockIdx.z * 32;

    int  hoff[5]; bool hval[5];
    #pragma unroll
    for (int k = 0; k < 5; k++) {
        int i = tid + k * 256;
        if (i < HALO) {
            int dz  = i / 360;
            int rem = i - dz * 360;
            int yy  = rem / 36;
            int xx  = rem - yy * 36;
            int z = zb + dz - 1, y = y0 + yy - 1, x = x0 + xx - 1;
            hval[k] = ((unsigned)z < D_) && ((unsigned)y < H_) && ((unsigned)x < W_) && (xx < 34);
            hoff[k] = z * HW + y * W_ + x;
        } else { hval[k] = false; hoff[k] = 0; }
    }
    int wbase[4]; bool wvalid[4];
    const int wstride = deconv ? Cout * 27 : 27;
    #pragma unroll
    for (int k = 0; k < 4; k++) {
        int idx = tid + k * 256;
        if (idx < WTOT) {
            int co = idx / 27, t = idx - co * 27;
            int coG = coBase + co;
            wvalid[k] = (coG < Cout);
            wbase[k]  = deconv ? (coG * 27 + (26 - t)) : (coG * Cin * 27 + t);
        } else { wvalid[k] = false; wbase[k] = 0; }
    }

    u64 acc[4][4];
    #pragma unroll
    for (int c = 0; c < 4; c++)
        #pragma unroll
        for (int j = 0; j < 4; j++) acc[c][j] = 0ull;

    float hreg[5], wreg[4];
    #pragma unroll
    for (int k = 0; k < 5; k++) hreg[k] = hval[k] ? __ldg(in + hoff[k]) : 0.f;
    #pragma unroll
    for (int k = 0; k < 4; k++) wreg[k] = wvalid[k] ? __ldg(w + wbase[k]) : 0.f;

    for (int ci = 0; ci < Cin; ci++) {
        #pragma unroll
        for (int k = 0; k < 5; k++) {
            int i = tid + k * 256;
            if (i < HALO) in_s[i] = hreg[k];
        }
        #pragma unroll
        for (int k = 0; k < 4; k++) {
            int idx = tid + k * 256;
            if (idx < WTOT) w_s2[idx] = make_float2(wreg[k], wreg[k]);
        }
        __syncthreads();

        if (ci + 1 < Cin) {
            const float* inp = in + (size_t)(ci + 1) * VOX;
            #pragma unroll
            for (int k = 0; k < 5; k++) hreg[k] = hval[k] ? __ldg(inp + hoff[k]) : 0.f;
            const float* wp_ = w + (size_t)(ci + 1) * wstride;
            #pragma unroll
            for (int k = 0; k < 4; k++) wreg[k] = wvalid[k] ? __ldg(wp_ + wbase[k]) : 0.f;
        }

        const float2* wp = &w_s2[cg * 4 * 27];
        #pragma unroll
        for (int dz = 0; dz < 3; dz++) {
            #pragma unroll
            for (int dy = 0; dy < 3; dy++) {
                const float* row = &in_s[(dz * 10 + ty + dy) * 36 + tx * 8];
                float4 a4 = *(const float4*)row;
                float4 b4 = *(const float4*)(row + 4);
                float2 c2 = *(const float2*)(row + 8);
                float v[10] = {a4.x, a4.y, a4.z, a4.w, b4.x, b4.y, b4.z, b4.w, c2.x, c2.y};
                u64 p[9];
                #pragma unroll
                for (int i = 0; i < 9; i++) p[i] = pk2(v[i], v[i + 1]);
                const int tb = dz * 9 + dy * 3;
                #pragma unroll
                for (int co = 0; co < 4; co++) {
                    const float2* wc = wp + co * 27 + tb;
                    u64 w0 = *(const u64*)(wc + 0);
                    fma2(acc[co][0], p[0], w0); fma2(acc[co][1], p[2], w0);
                    fma2(acc[co][2], p[4], w0); fma2(acc[co][3], p[6], w0);
                    u64 w1 = *(const u64*)(wc + 1);
                    fma2(acc[co][0], p[1], w1); fma2(acc[co][1], p[3], w1);
                    fma2(acc[co][2], p[5], w1); fma2(acc[co][3], p[7], w1);
                    u64 w2 = *(const u64*)(wc + 2);
                    fma2(acc[co][0], p[2], w2); fma2(acc[co][1], p[4], w2);
                    fma2(acc[co][2], p[6], w2); fma2(acc[co][3], p[8], w2);
                }
            }
        }
        __syncthreads();
    }

    const int xo = x0 + tx * 8;
    const size_t base = (size_t)zb * HW + (y0 + ty) * W_ + xo;
    #pragma unroll
    for (int co = 0; co < 4; co++) {
        int coG = coBase + cg * 4 + co;
        if (coG < Cout) {
            float2 q0 = unpk2(acc[co][0]);
            float2 q1 = unpk2(acc[co][1]);
            float2 q2 = unpk2(acc[co][2]);
            float2 q3 = unpk2(acc[co][3]);
            float* op = out + (size_t)coG * VOX + base;
            *(float4*)(op + 0) = make_float4(q0.x, q0.y, q1.x, q1.y);
            *(float4*)(op + 4) = make_float4(q2.x, q2.y, q3.x, q3.y);
        }
    }
}

// ============================ SRU kernels ============================
__global__ void si_sru_k(const float* __restrict__ g, float* __restrict__ out,
                         const float* __restrict__ add, int C, int rev)
{
    int tid = blockIdx.x * blockDim.x + threadIdx.x;
    int total = C * HW;
    if (tid >= total) return;
    int c  = tid / HW;
    int yx = tid - c * HW;

    const float* Wp = g + (size_t)(0 * C + c) * VOX + yx;
    const float* Fp = g + (size_t)(1 * C + c) * VOX + yx;
    const float* Rp = g + (size_t)(2 * C + c) * VOX + yx;
    const float* Xp = g + (size_t)(3 * C + c) * VOX + yx;
    float*       op = out + (size_t)c * VOX + yx;
    const float* ap = add ? add + (size_t)c * VOX + yx : nullptr;

    int off = rev ? (D_ - 1) * HW : 0;
    int zs  = rev ? -HW : HW;

    float f = sigm(Fp[off]);
    float Cc = 1.f - f;
    float r = sigm(Rp[off]);
    float h = r * Cc + (1.f - r) * tanhf(Xp[off]);
    op[off] = h + (ap ? ap[off] : 0.f);

    for (int t = 1; t < D_; t++) {
        off += zs;
        f  = sigm(Fp[off]);
        Cc = f * Cc + (1.f - f) * tanhf(Wp[off]);
        r  = sigm(Rp[off]);
        h  = r * Cc + (1.f - r) * tanhf(Xp[off]);
        op[off] = h + (ap ? ap[off] : 0.f);
    }
}

__global__ void do_sru_k(const float* __restrict__ g, float* __restrict__ out,
                         const float* __restrict__ add, int C)
{
    int tid = blockIdx.x * blockDim.x + threadIdx.x;
    int total = C * HW;
    if (tid >= total) return;
    int c  = tid / HW;
    int yx = tid - c * HW;

    const float* Wp = g + (size_t)(0 * C + c) * VOX + yx;
    const float* F1 = g + (size_t)(1 * C + c) * VOX + yx;
    const float* F2 = g + (size_t)(2 * C + c) * VOX + yx;
    const float* R1 = g + (size_t)(3 * C + c) * VOX + yx;
    const float* R2 = g + (size_t)(4 * C + c) * VOX + yx;
    const float* Xp = g + (size_t)(5 * C + c) * VOX + yx;
    float*       op = out + (size_t)c * VOX + yx;
    const float* ap = add ? add + (size_t)c * VOX + yx : nullptr;

    {
        float f = sigm(F1[0]);
        float Cc = 1.f - f;
        float r = sigm(R1[0]);
        op[0] = r * Cc + (1.f - r) * tanhf(Xp[0]);
        int off = 0;
        for (int t = 1; t < D_; t++) {
            off += HW;
            f  = sigm(F1[off]);
            Cc = f * Cc + (1.f - f) * tanhf(Wp[off]);
            r  = sigm(R1[off]);
            op[off] = r * Cc + (1.f - r) * tanhf(Xp[off]);
        }
    }
    {
        int off = (D_ - 1) * HW;
        float f = sigm(F2[off]);
        float Cc = 1.f - f;
        float r = sigm(R2[off]);
        float h = r * Cc + (1.f - r) * tanhf(Xp[off]);
        op[off] = op[off] + h + (ap ? ap[off] : 0.f);
        for (int t = 1; t < D_; t++) {
            off -= HW;
            f  = sigm(F2[off]);
            Cc = f * Cc + (1.f - f) * tanhf(Wp[off]);
            r  = sigm(R2[off]);
            h  = r * Cc + (1.f - r) * tanhf(Xp[off]);
            op[off] = op[off] + h + (ap ? ap[off] : 0.f);
        }
    }
}

// ============================ host ============================
static __nv_bfloat16 *s_Ahi, *s_Alo;

static inline void conv_tc(const float* in, const float* w, float* out,
                           int Cin, int Cout, int deconv)
{
    int Kpad = Cin * 32;
    int total = Cout * Kpad;
    prep_k<<<(total + 255) / 256, 256>>>(w, s_Ahi, s_Alo, Cin, Cout, Kpad, deconv, total);
    dim3 grid(D_ * 48, Cout / 64);
    conv_mma_k<<<grid, 256>>>(in, s_Ahi, s_Alo, out, Cin, Kpad, Cin * 2);
}

static inline void conv_scalar(const float* in, const float* w, float* out,
                               int Cin, int Cout, int deconv)
{
    dim3 grid(W_ / 32, (H_ / 8) * D_, (Cout + 31) / 32);
    conv3d_k<<<grid, 256>>>(in, w, out, Cin, Cout, deconv);
}

static inline void si_launch(const float* gbuf, float* out, const float* add, int C, int rev)
{
    int n = C * HW;
    si_sru_k<<<(n + 255) / 256, 256>>>(gbuf, out, add, C, rev);
}
static inline void do_launch(const float* gbuf, float* out, const float* add, int C)
{
    int n = C * HW;
    do_sru_k<<<(n + 255) / 256, 256>>>(gbuf, out, add, C);
}

extern "C" void kernel_launch(void* const* d_in, const int* in_sizes, int n_in,
                              void* d_out, int out_size)
{
    (void)in_sizes; (void)n_in; (void)out_size;
    const float* x      = (const float*)d_in[0];
    const float* w_head = (const float*)d_in[1];
    const float* w_e0   = (const float*)d_in[2];
    const float* w_e1   = (const float*)d_in[3];
    const float* w_d0   = (const float*)d_in[4];
    const float* w_d1   = (const float*)d_in[5];
    const float* w_tail = (const float*)d_in[6];
    float* out = (float*)d_out;

    float *gc, *gh, *ge0, *ge1, *gd0, *gd1;
    cudaGetSymbolAddress((void**)&gc,  g_conv);
    cudaGetSymbolAddress((void**)&gh,  g_h);
    cudaGetSymbolAddress((void**)&ge0, g_e0);
    cudaGetSymbolAddress((void**)&ge1, g_e1);
    cudaGetSymbolAddress((void**)&gd0, g_d0);
    cudaGetSymbolAddress((void**)&gd1, g_d1);
    cudaGetSymbolAddress((void**)&s_Ahi, g_Ahi);
    cudaGetSymbolAddress((void**)&s_Alo, g_Alo);

    // h = do_sru(x, w_head)          (scalar: Cin=1)
    conv_scalar(x, w_head, gc, 1, 96, 0);
    do_launch(gc, gh, nullptr, 16);
    // e0 = si_sru(h, w_e0, fwd)      (mma: 16 -> 128)
    conv_tc(gh, w_e0, gc, 16, 128, 0);
    si_launch(gc, ge0, nullptr, 32, 0);
    // e1 = si_sru(e0, w_e1, rev)     (mma: 32 -> 256)
    conv_tc(ge0, w_e1, gc, 32, 256, 0);
    si_launch(gc, ge1, nullptr, 64, 1);
    // d0 = si_sru(e1, w_d0, fwd, deconv) + e0   (mma: 64 -> 128)
    conv_tc(ge1, w_d0, gc, 64, 128, 1);
    si_launch(gc, gd0, ge0, 32, 0);
    // d1 = si_sru(d0, w_d1, rev, deconv) + h    (mma: 32 -> 64)
    conv_tc(gd0, w_d1, gc, 32, 64, 1);
    si_launch(gc, gd1, gh, 16, 1);
    // out = do_sru(d1, w_tail, deconv) + x      (scalar: Cout=6)
    conv_scalar(gd1, w_tail, gc, 16, 6, 1);
    do_launch(gc, out, x, 1);
}